// round 5
// baseline (speedup 1.0000x reference)
#include <cuda_runtime.h>
#include <math.h>
#include <stdint.h>

#define XP    16386
#define XS    16640          // row stride (65*256)
#define NXV   16384
#define KPAD  16416          // forward-DFT K extent (16*1024 + 32)
#define NB    16

// ------------------- static device buffers -------------------
__device__ float d_h   [(size_t)NB * 64 * XS];
__device__ float d_h2  [(size_t)NB * 64 * XS];
__device__ float d_g   [(size_t)NB * 64 * XS];
__device__ float d_gmid[(size_t)NB * 128 * XS];
__device__ float d_ftab[(size_t)KPAD * 128];      // [x][2m]=cos, [2m+1]=-sin
__device__ float d_itab[(size_t)128 * XS];        // [2m][x]=cos, [2m+1][x]=sin
__device__ float d_part[(size_t)17 * 2048 * 128];
__device__ float d_fw  [2048 * 128];
__device__ float d_outm[1024 * 128];
__device__ float d_coefW[64 * 64];                // aw * W for current block
__device__ float d_w1T [4 * 64 * 128];
__device__ float d_w2T [4 * 128 * 64];
__device__ float d_fc1T[64 * 128];

// ------------------- helpers -------------------
__device__ __forceinline__ uint64_t pack2(float lo, float hi) {
    uint64_t r;
    asm("mov.b64 %0, {%1, %2};" : "=l"(r) : "f"(lo), "f"(hi));
    return r;
}
__device__ __forceinline__ void unpack2(uint64_t v, float& lo, float& hi) {
    asm("mov.b64 {%0, %1}, %2;" : "=f"(lo), "=f"(hi) : "l"(v));
}
#define FMA2(d, a, b) \
    asm("fma.rn.f32x2 %0, %1, %2, %0;" : "+l"(d) : "l"(a), "l"(b))

__device__ __forceinline__ uint32_t s2u(const void* p) {
    return (uint32_t)__cvta_generic_to_shared(p);
}
__device__ __forceinline__ void cp16(uint32_t s, const float* g) {
    asm volatile("cp.async.cg.shared.global [%0], [%1], 16;"
                 :: "r"(s), "l"(__cvta_generic_to_global(g)));
}
#define CP_COMMIT asm volatile("cp.async.commit_group;")
#define CP_WAIT(n) asm volatile("cp.async.wait_group %0;" :: "n"(n))

__device__ __forceinline__ float softplus_(float x) {
    return (x > 20.f) ? x : log1pf(expf(x));
}
__device__ __forceinline__ float gelu_(float v) {
    return 0.5f * v * (1.0f + erff(v * 0.70710678118654752f));
}

// ------------------- table init -------------------
__global__ void init_ftab_kernel() {
    int idx = blockIdx.x * 256 + threadIdx.x;
    if (idx >= KPAD * 128) return;
    int x = idx >> 7, t = idx & 127, m = t >> 1;
    float v = 0.f;
    if (x < XP) {
        int u = (x * m) % XP;
        float s, c;
        sincospif(2.0f * (float)u / (float)XP, &s, &c);
        v = (t & 1) ? -s : c;
    }
    d_ftab[idx] = v;
}

__global__ void init_itab_kernel() {
    int idx = blockIdx.x * 256 + threadIdx.x;
    if (idx >= 128 * XS) return;
    int t = idx / XS, x = idx - t * XS, m = t >> 1;
    float v = 0.f;
    if (x < XP) {
        int u = (x * m) % XP;
        float s, c;
        sincospif(2.0f * (float)u / (float)XP, &s, &c);
        v = (t & 1) ? s : c;
    }
    d_itab[idx] = v;
}

// ------------------- weight transposes -------------------
__global__ void prep_weights_kernel(const float* __restrict__ g_w1,
                                    const float* __restrict__ g_w2,
                                    const float* __restrict__ fc1_w) {
    int idx = blockIdx.x * 256 + threadIdx.x;
    if (idx < 32768) {
        int i = idx >> 13, r = idx & 8191, c = r >> 7, j = r & 127;
        d_w1T[idx] = g_w1[(i * 128 + j) * 64 + c];
    } else if (idx < 65536) {
        int t = idx - 32768;
        int i = t >> 13, r = t & 8191, j = r >> 6, o = r & 63;
        d_w2T[t] = g_w2[(i * 64 + o) * 128 + j];
    } else if (idx < 73728) {
        int t = idx - 65536;
        int c = t >> 7, j = t & 127;
        d_fc1T[t] = fc1_w[j * 64 + c];
    }
}

__global__ void zero_tail_kernel() {
    int idx = blockIdx.x * 256 + threadIdx.x;    // 1024 rows x 256 tail cols
    int row = idx >> 8, col = NXV + (idx & 255);
    d_h[(size_t)row * XS + col] = 0.f;
}

__global__ void coefw_kernel(const float* __restrict__ w_w,
                             const float* __restrict__ alpha_w, int blk) {
    int i = blockIdx.x * 256 + threadIdx.x;      // 4096
    d_coefW[i] = softplus_(__ldg(alpha_w)) * __ldg(&w_w[blk * 4096 + i]);
}

// ------------------- fc0 -------------------
__global__ void __launch_bounds__(128) fc0_kernel(const float* __restrict__ xin,
                                                  const float* __restrict__ gin,
                                                  const float* __restrict__ w,
                                                  const float* __restrict__ bias) {
    __shared__ float sw[64 * 32];
    __shared__ float sb[64];
    int tid = threadIdx.x;
    for (int l = tid; l < 64 * 31; l += 128) {
        int wo = l / 31, c = l - wo * 31;
        sw[wo * 32 + c] = w[l];
    }
    if (tid < 64) sb[tid] = bias[tid];
    __syncthreads();
    int b = blockIdx.y;
    int x = blockIdx.x * 128 + tid;
    float rin[31];
    const float* xi = xin + ((size_t)b * NXV + x) * 30;
#pragma unroll
    for (int c = 0; c < 30; c++) rin[c] = __ldg(&xi[c]);
    rin[30] = __ldg(&gin[(size_t)b * NXV + x]);
    for (int wo = 0; wo < 64; wo++) {
        float acc = sb[wo];
#pragma unroll
        for (int c = 0; c < 31; c++) acc = fmaf(rin[c], sw[wo * 32 + c], acc);
        d_h[(size_t)(b * 64 + wo) * XS + x] = acc;
    }
}

// ------------------- 1x1 conv (cp.async double-buffered, f32x2) -------------------
// ACT: 0=none, 1=gelu, 2=scale by softplus(*alpha)
template<int CIN, int COUT, int ACT>
__global__ void __launch_bounds__(256, 2) conv1x1_kernel(
    const float* __restrict__ in,    // [b*CIN + c][XS]
    const float* __restrict__ wT,    // [CIN][COUT]
    const float* __restrict__ bias,  // [COUT]
    float* __restrict__ out,         // [b*COUT + o][XS]
    const float* __restrict__ alpha)
{
    constexpr int BP  = (COUT >= 128) ? 128 : 256;  // positions per block
    constexpr int TPp = BP / 32;                    // pos per thread (4/8)
    constexpr int TOc = COUT / 8;                   // outs per thread (16/8)
    constexpr int OP  = TOc / 2;                    // out pairs (8/4)
    constexpr int NTt = CIN / 16;
    constexpr int SIC = (16 * BP / 4) / 256;        // si chunks/thread
    constexpr int SWC = (16 * COUT / 4) / 256;      // swt chunks/thread
    __shared__ float si [2][16][BP];
    __shared__ float swt[2][16][COUT];
    const int b   = blockIdx.y;
    const int p0  = blockIdx.x * BP;
    const int tid = threadIdx.x;
    const int po  = (tid & 31) * TPp;
    const int oo  = (tid >> 5) * TOc;

    const float* inb = in + (size_t)b * CIN * XS + p0;

    uint64_t acc[TPp][OP];
#pragma unroll
    for (int p = 0; p < TPp; p++)
#pragma unroll
        for (int j = 0; j < OP; j++) acc[p][j] = 0ull;

    // stage tile 0
    {
#pragma unroll
        for (int l = 0; l < SIC; l++) {
            int c = l * 256 + tid;
            int k = c / (BP / 4), q = (c % (BP / 4)) * 4;
            cp16(s2u(&si[0][k][q]), inb + k * XS + q);
        }
#pragma unroll
        for (int l = 0; l < SWC; l++) {
            int c = l * 256 + tid;
            int k = c / (COUT / 4), q = (c % (COUT / 4)) * 4;
            cp16(s2u(&swt[0][k][q]), wT + k * COUT + q);
        }
        CP_COMMIT;
    }
#pragma unroll
    for (int t = 0; t < NTt; t++) {
        const int buf = t & 1;
        if (t + 1 < NTt) {
            const int c0 = (t + 1) * 16;
#pragma unroll
            for (int l = 0; l < SIC; l++) {
                int c = l * 256 + tid;
                int k = c / (BP / 4), q = (c % (BP / 4)) * 4;
                cp16(s2u(&si[buf ^ 1][k][q]), inb + (c0 + k) * XS + q);
            }
#pragma unroll
            for (int l = 0; l < SWC; l++) {
                int c = l * 256 + tid;
                int k = c / (COUT / 4), q = (c % (COUT / 4)) * 4;
                cp16(s2u(&swt[buf ^ 1][k][q]), wT + (c0 + k) * COUT + q);
            }
            CP_COMMIT;
            CP_WAIT(1);
        } else {
            CP_WAIT(0);
        }
        __syncthreads();
#pragma unroll
        for (int k = 0; k < 16; k++) {
            uint64_t pa[TPp];
#pragma unroll
            for (int u = 0; u < TPp / 4; u++) {
                float4 av = *(const float4*)&si[buf][k][po + 4 * u];
                pa[4*u+0] = pack2(av.x, av.x);
                pa[4*u+1] = pack2(av.y, av.y);
                pa[4*u+2] = pack2(av.z, av.z);
                pa[4*u+3] = pack2(av.w, av.w);
            }
#pragma unroll
            for (int j = 0; j < OP; j++) {
                uint64_t wv = *(const uint64_t*)&swt[buf][k][oo + 2 * j];
#pragma unroll
                for (int p = 0; p < TPp; p++) FMA2(acc[p][j], wv, pa[p]);
            }
        }
        __syncthreads();
    }

    float scv = 1.f;
    if (ACT == 2) scv = softplus_(__ldg(alpha));
#pragma unroll
    for (int j = 0; j < OP; j++) {
        int o0 = oo + 2 * j;
        float b0 = __ldg(&bias[o0]);
        float b1 = __ldg(&bias[o0 + 1]);
        float vlo[TPp], vhi[TPp];
#pragma unroll
        for (int p = 0; p < TPp; p++) {
            unpack2(acc[p][j], vlo[p], vhi[p]);
            vlo[p] += b0; vhi[p] += b1;
            if (ACT == 1) { vlo[p] = gelu_(vlo[p]); vhi[p] = gelu_(vhi[p]); }
            if (ACT == 2) { vlo[p] *= scv; vhi[p] *= scv; }
        }
        float* r0 = out + ((size_t)b * COUT + o0) * XS + p0 + po;
        float* r1 = r0 + XS;
#pragma unroll
        for (int q = 0; q < TPp / 4; q++) {
            *(float4*)&r0[4*q] = make_float4(vlo[4*q], vlo[4*q+1], vlo[4*q+2], vlo[4*q+3]);
            *(float4*)&r1[4*q] = make_float4(vhi[4*q], vhi[4*q+1], vhi[4*q+2], vhi[4*q+3]);
        }
    }
}

// ------------------- forward DFT (split-K, cp.async pipelined) -------------------
__global__ void __launch_bounds__(256, 2) fdft_kernel(const float* __restrict__ hcur) {
    const int rt = blockIdx.x;     // 0..15 : 128-row tiles (8 h, 8 g)
    const int ks = blockIdx.y;     // 0..16
    const float* src = (rt < 8) ? hcur + (size_t)rt * 128 * XS
                                : d_g + (size_t)(rt - 8) * 128 * XS;
    const int kbase = ks * 1024;
    const int NTt = (ks == 16) ? 2 : 64;

    __shared__ float sa[2][128][16];   // [row][k]
    __shared__ float sb[2][16][128];   // [k][mode-comp]
    const int tid = threadIdx.x;
    const int mo = (tid & 7) * 16;
    const int rg = (tid >> 3) * 4;

    uint64_t acc[4][8];
#pragma unroll
    for (int r = 0; r < 4; r++)
#pragma unroll
        for (int j = 0; j < 8; j++) acc[r][j] = 0ull;

    {
#pragma unroll
        for (int l = 0; l < 2; l++) {
            int c = l * 256 + tid;
            int row = c >> 2, q = (c & 3) * 4;
            cp16(s2u(&sa[0][row][q]), src + row * XS + kbase + q);
            int k = c >> 5, q2 = (c & 31) * 4;
            cp16(s2u(&sb[0][k][q2]), d_ftab + (kbase + k) * 128 + q2);
        }
        CP_COMMIT;
    }
    for (int t = 0; t < NTt; t++) {
        const int buf = t & 1;
        if (t + 1 < NTt) {
            const int kb = kbase + (t + 1) * 16;
#pragma unroll
            for (int l = 0; l < 2; l++) {
                int c = l * 256 + tid;
                int row = c >> 2, q = (c & 3) * 4;
                cp16(s2u(&sa[buf ^ 1][row][q]), src + row * XS + kb + q);
                int k = c >> 5, q2 = (c & 31) * 4;
                cp16(s2u(&sb[buf ^ 1][k][q2]), d_ftab + (kb + k) * 128 + q2);
            }
            CP_COMMIT;
            CP_WAIT(1);
        } else {
            CP_WAIT(0);
        }
        __syncthreads();
#pragma unroll
        for (int k = 0; k < 16; k++) {
            uint64_t bv[8];
#pragma unroll
            for (int j = 0; j < 8; j++)
                bv[j] = *(const uint64_t*)&sb[buf][k][mo + 2 * j];
#pragma unroll
            for (int r = 0; r < 4; r++) {
                float a = sa[buf][rg + r][k];
                uint64_t pa = pack2(a, a);
#pragma unroll
                for (int j = 0; j < 8; j++) FMA2(acc[r][j], pa, bv[j]);
            }
        }
        __syncthreads();
    }
#pragma unroll
    for (int r = 0; r < 4; r++) {
        float v[16];
#pragma unroll
        for (int j = 0; j < 8; j++) unpack2(acc[r][j], v[2*j], v[2*j+1]);
        int orow = ks * 2048 + rt * 128 + rg + r;
        float* pp = &d_part[(size_t)orow * 128 + mo];
#pragma unroll
        for (int q = 0; q < 4; q++)
            *(float4*)&pp[4*q] = make_float4(v[4*q], v[4*q+1], v[4*q+2], v[4*q+3]);
    }
}

__global__ void reduce_kernel() {
    int idx = blockIdx.x * 256 + threadIdx.x;   // 262144
    float s = 0.f;
#pragma unroll
    for (int k = 0; k < 17; k++) s += d_part[(size_t)k * 262144 + idx];
    d_fw[idx] = s;
}

// ------------------- mode mix + ETD coefficients (bias folded) -------------------
__global__ void __launch_bounds__(512) modemix_kernel(const float* __restrict__ mix_re,
                                                      const float* __restrict__ mix_im,
                                                      const float* __restrict__ log_decay,
                                                      const float* __restrict__ w_b,
                                                      const float* __restrict__ alpha_w,
                                                      int blk) {
    __shared__ float sg[64 * 128];
    const int b  = blockIdx.x;
    const int og = blockIdx.y;
    const int tid = threadIdx.x;
#pragma unroll
    for (int l = 0; l < 16; l++) {
        int idx = l * 512 + tid;
        sg[idx] = d_fw[(size_t)(1024 + b * 64) * 128 + idx];
    }
    __syncthreads();
    const int m = tid & 63, ol = tid >> 6;
    const int o = og * 8 + ol;
    const float* mr = mix_re + (size_t)blk * 262144 + o * 64 + m;
    const float* mi = mix_im + (size_t)blk * 262144 + o * 64 + m;
    float ar = 0.f, ai = 0.f;
#pragma unroll 4
    for (int i = 0; i < 64; i++) {
        float2 gh = *(const float2*)&sg[i * 128 + 2 * m];
        float r_ = __ldg(&mr[(size_t)i * 4096]);
        float i_ = __ldg(&mi[(size_t)i * 4096]);
        ar = fmaf(gh.x, r_, ar); ar = fmaf(-gh.y, i_, ar);
        ai = fmaf(gh.x, i_, ai); ai = fmaf( gh.y, r_, ai);
    }
    float ld = __ldg(&log_decay[((size_t)blk * 64 + o) * 64 + m]);
    float z  = -softplus_(ld);
    float ez = expf(z);
    float phi = (fabsf(z) < 1e-6f) ? (1.f + 0.5f * z + z * z * (1.f / 6.f))
                                   : (expm1f(z) / z);
    float gq = (float)m * (1.f / 63.f);
    float r2 = gq * gq + 1e-12f;
    float r8 = r2 * r2; r8 = r8 * r8;
    float pf = phi * expf(-2.f * r8);

    size_t vrow = ((size_t)b * 64 + o) * 128;
    float vr = d_fw[vrow + 2 * m], vi = d_fw[vrow + 2 * m + 1];
    float outr = fmaf(ez, vr, pf * ar);
    float outi = fmaf(ez, vi, pf * ai);
    const float inv = 1.0f / 16386.0f;
    float resr = (m == 0) ? outr * inv : 2.f * outr * inv;
    if (m == 0) resr += softplus_(__ldg(alpha_w)) * __ldg(&w_b[blk * 64 + o]);
    d_outm[vrow + 2 * m]     = resr;
    d_outm[vrow + 2 * m + 1] = (m == 0) ? 0.f : -2.f * outi * inv;
}

// ---------- inverse DFT + fused w-skip + activation (K=192, pipelined) ----------
__global__ void __launch_bounds__(256, 2) idft_kernel(const float* __restrict__ hsrc,
                                                      float* __restrict__ dst, int act) {
    const int x0 = blockIdx.x * 256;
    const int b  = blockIdx.y;
    __shared__ float st[2][16][256];   // [k][x] : itab rows or h rows
    __shared__ float sc[2][64][16];    // [row][k]
    const int tid = threadIdx.x;
    const int xg = (tid & 15) * 16;
    const int rg = (tid >> 4) * 4;
    const float* hb = hsrc + (size_t)b * 64 * XS;

    uint64_t acc[4][8];
#pragma unroll
    for (int r = 0; r < 4; r++)
#pragma unroll
        for (int j = 0; j < 8; j++) acc[r][j] = 0ull;

    // stage tile 0 (itab k 0..15, coefs from d_outm)
    {
#pragma unroll
        for (int l = 0; l < 4; l++) {
            int c = l * 256 + tid;
            int k = c >> 6, q = (c & 63) * 4;
            cp16(s2u(&st[0][k][q]), d_itab + k * XS + x0 + q);
        }
        int row = tid >> 2, q = (tid & 3) * 4;
        cp16(s2u(&sc[0][row][q]), d_outm + (b * 64 + row) * 128 + q);
        CP_COMMIT;
    }
#pragma unroll
    for (int t = 0; t < 12; t++) {
        const int buf = t & 1;
        if (t + 1 < 12) {
            const int kb = (t + 1) * 16;
#pragma unroll
            for (int l = 0; l < 4; l++) {
                int c = l * 256 + tid;
                int k = c >> 6, q = (c & 63) * 4;
                const float* gsrc = (t + 1 < 8)
                    ? d_itab + (kb + k) * XS + x0 + q
                    : hb + (kb - 128 + k) * XS + x0 + q;
                cp16(s2u(&st[buf ^ 1][k][q]), gsrc);
            }
            {
                int row = tid >> 2, q = (tid & 3) * 4;
                const float* gsrc = (t + 1 < 8)
                    ? d_outm + (b * 64 + row) * 128 + kb + q
                    : d_coefW + row * 64 + (kb - 128) + q;
                cp16(s2u(&sc[buf ^ 1][row][q]), gsrc);
            }
            CP_COMMIT;
            CP_WAIT(1);
        } else {
            CP_WAIT(0);
        }
        __syncthreads();
#pragma unroll
        for (int k = 0; k < 16; k++) {
            uint64_t tv[8];
#pragma unroll
            for (int j = 0; j < 8; j++)
                tv[j] = *(const uint64_t*)&st[buf][k][xg + 2 * j];
#pragma unroll
            for (int r = 0; r < 4; r++) {
                float a = sc[buf][rg + r][k];
                uint64_t pa = pack2(a, a);
#pragma unroll
                for (int j = 0; j < 8; j++) FMA2(acc[r][j], pa, tv[j]);
            }
        }
        __syncthreads();
    }
#pragma unroll
    for (int r = 0; r < 4; r++) {
        float v[16];
#pragma unroll
        for (int j = 0; j < 8; j++) unpack2(acc[r][j], v[2*j], v[2*j+1]);
        if (act) {
#pragma unroll
            for (int j = 0; j < 16; j++) v[j] = gelu_(v[j]);
        }
        float* pp = dst + ((size_t)b * 64 + rg + r) * XS + x0 + xg;
#pragma unroll
        for (int q = 0; q < 4; q++)
            *(float4*)&pp[4*q] = make_float4(v[4*q], v[4*q+1], v[4*q+2], v[4*q+3]);
    }
}

// ------------------- fc2 -------------------
__global__ void __launch_bounds__(128) fc2_kernel(const float* __restrict__ w,
                                                  const float* __restrict__ bias,
                                                  float* __restrict__ out) {
    __shared__ float sw[3][128];
    int tid = threadIdx.x;
    for (int l = tid; l < 384; l += 128) sw[l >> 7][l & 127] = w[l];
    __syncthreads();
    int b = blockIdx.y;
    int x = blockIdx.x * 128 + tid;
    float a0 = __ldg(&bias[0]), a1 = __ldg(&bias[1]), a2 = __ldg(&bias[2]);
#pragma unroll 4
    for (int j = 0; j < 128; j++) {
        float v = d_gmid[((size_t)b * 128 + j) * XS + x];
        a0 = fmaf(v, sw[0][j], a0);
        a1 = fmaf(v, sw[1][j], a1);
        a2 = fmaf(v, sw[2][j], a2);
    }
    size_t o = ((size_t)b * NXV + x) * 3;
    out[o] = a0; out[o + 1] = a1; out[o + 2] = a2;
}

// ------------------- launch -------------------
extern "C" void kernel_launch(void* const* d_in, const int* in_sizes, int n_in,
                              void* d_out, int out_size) {
    const float* x_in   = (const float*)d_in[0];
    const float* grid   = (const float*)d_in[1];
    const float* fc0_w  = (const float*)d_in[2];
    const float* fc0_b  = (const float*)d_in[3];
    const float* fc1_w  = (const float*)d_in[4];
    const float* fc1_b  = (const float*)d_in[5];
    const float* fc2_w  = (const float*)d_in[6];
    const float* fc2_b  = (const float*)d_in[7];
    const float* g_w1   = (const float*)d_in[8];
    const float* g_b1   = (const float*)d_in[9];
    const float* g_w2   = (const float*)d_in[10];
    const float* g_b2   = (const float*)d_in[11];
    const float* w_w    = (const float*)d_in[12];
    const float* w_b    = (const float*)d_in[13];
    const float* ldcy   = (const float*)d_in[14];
    const float* mix_re = (const float*)d_in[15];
    const float* mix_im = (const float*)d_in[16];
    const float* aw     = (const float*)d_in[17];
    const float* ag     = (const float*)d_in[18];

    float *phA, *phB, *pg, *pgmid, *pw1T, *pw2T, *pfc1T;
    cudaGetSymbolAddress((void**)&phA,   d_h);
    cudaGetSymbolAddress((void**)&phB,   d_h2);
    cudaGetSymbolAddress((void**)&pg,    d_g);
    cudaGetSymbolAddress((void**)&pgmid, d_gmid);
    cudaGetSymbolAddress((void**)&pw1T,  d_w1T);
    cudaGetSymbolAddress((void**)&pw2T,  d_w2T);
    cudaGetSymbolAddress((void**)&pfc1T, d_fc1T);

    fc0_kernel<<<dim3(128, 16), 128>>>(x_in, grid, fc0_w, fc0_b);
    zero_tail_kernel<<<1024, 256>>>();
    prep_weights_kernel<<<288, 256>>>(g_w1, g_w2, fc1_w);

    float* cur = phA;
    float* nxt = phB;
    for (int i = 0; i < 4; i++) {
        conv1x1_kernel<64, 128, 1><<<dim3(129, 16), 256>>>(
            cur, pw1T + i * 8192, g_b1 + i * 128, pgmid, nullptr);
        if (i == 0) {
            init_ftab_kernel<<<(KPAD * 128 + 255) / 256, 256>>>();
            init_itab_kernel<<<(128 * XS + 255) / 256, 256>>>();
        }
        conv1x1_kernel<128, 64, 2><<<dim3(65, 16), 256>>>(
            pgmid, pw2T + i * 8192, g_b2 + i * 64, pg, ag);
        fdft_kernel<<<dim3(16, 17), 256>>>(cur);
        reduce_kernel<<<1024, 256>>>();
        coefw_kernel<<<16, 256>>>(w_w, aw, i);
        modemix_kernel<<<dim3(16, 8), 512>>>(mix_re, mix_im, ldcy, w_b, aw, i);
        idft_kernel<<<dim3(65, 16), 256>>>(cur, nxt, (i < 3) ? 1 : 0);
        float* tmp = cur; cur = nxt; nxt = tmp;
    }

    conv1x1_kernel<64, 128, 1><<<dim3(128, 16), 256>>>(
        cur, pfc1T, fc1_b, pgmid, nullptr);
    fc2_kernel<<<dim3(128, 16), 128>>>(fc2_w, fc2_b, (float*)d_out);
}

// round 6
// speedup vs baseline: 1.8023x; 1.8023x over previous
#include <cuda_runtime.h>
#include <math.h>
#include <stdint.h>

#define XP    16386
#define XS    16640          // row stride (65*256)
#define NXV   16384
#define KPAD  16416          // forward-DFT K: 16*1024 + 32
#define NB    16

// ------------------- static device buffers -------------------
__device__ float d_h   [(size_t)NB * 64 * XS];
__device__ float d_g   [(size_t)NB * 64 * XS];
__device__ float d_gmid[(size_t)NB * 128 * XS];
__device__ float d_wout[(size_t)NB * 64 * XS];
__device__ float d_ftab[(size_t)KPAD * 128];      // [x][2m]=cos, [2m+1]=-sin
__device__ float d_itab[(size_t)128 * XS];        // [2m][x]=cos, [2m+1][x]=sin
__device__ float d_part[(size_t)17 * 2048 * 128];
__device__ float d_fw  [2048 * 128];
__device__ float d_outm[1024 * 128];
__device__ float d_w1T [4 * 64 * 128];
__device__ float d_w2T [4 * 128 * 64];
__device__ float d_wwT [4 * 64 * 64];
__device__ float d_fc1T[64 * 128];

// ------------------- f32x2 packed helpers -------------------
__device__ __forceinline__ uint64_t pack2(float lo, float hi) {
    uint64_t r;
    asm("mov.b64 %0, {%1, %2};" : "=l"(r) : "f"(lo), "f"(hi));
    return r;
}
__device__ __forceinline__ void unpack2(uint64_t v, float& lo, float& hi) {
    asm("mov.b64 {%0, %1}, %2;" : "=f"(lo), "=f"(hi) : "l"(v));
}
#define FMA2(d, a, b) \
    asm("fma.rn.f32x2 %0, %1, %2, %0;" : "+l"(d) : "l"(a), "l"(b))

__device__ __forceinline__ uint32_t s2u(const void* p) {
    return (uint32_t)__cvta_generic_to_shared(p);
}
__device__ __forceinline__ void cp16(uint32_t s, const float* g) {
    asm volatile("cp.async.cg.shared.global [%0], [%1], 16;"
                 :: "r"(s), "l"(__cvta_generic_to_global(g)));
}
#define CP_COMMIT asm volatile("cp.async.commit_group;")
#define CP_WAIT(n) asm volatile("cp.async.wait_group %0;" :: "n"(n))

__device__ __forceinline__ float softplus_(float x) {
    return (x > 20.f) ? x : log1pf(expf(x));
}
__device__ __forceinline__ float gelu_(float v) {
    return 0.5f * v * (1.0f + erff(v * 0.70710678118654752f));
}

// ------------------- table init -------------------
__global__ void init_ftab_kernel() {
    int idx = blockIdx.x * 256 + threadIdx.x;
    if (idx >= KPAD * 128) return;
    int x = idx >> 7, t = idx & 127, m = t >> 1;
    float v = 0.f;
    if (x < XP) {
        int u = (x * m) % XP;
        float s, c;
        sincospif(2.0f * (float)u / (float)XP, &s, &c);
        v = (t & 1) ? -s : c;
    }
    d_ftab[idx] = v;
}

__global__ void init_itab_kernel() {
    int idx = blockIdx.x * 256 + threadIdx.x;
    if (idx >= 128 * XS) return;
    int t = idx / XS, x = idx - t * XS, m = t >> 1;
    float v = 0.f;
    if (x < XP) {
        int u = (x * m) % XP;
        float s, c;
        sincospif(2.0f * (float)u / (float)XP, &s, &c);
        v = (t & 1) ? s : c;
    }
    d_itab[idx] = v;
}

// ------------------- weight transposes -------------------
__global__ void prep_weights_kernel(const float* __restrict__ g_w1,
                                    const float* __restrict__ g_w2,
                                    const float* __restrict__ w_w,
                                    const float* __restrict__ fc1_w) {
    int idx = blockIdx.x * 256 + threadIdx.x;
    if (idx < 32768) {                           // w1T[i][c][j] = g_w1[i][j][c]
        int i = idx >> 13, r = idx & 8191, c = r >> 7, j = r & 127;
        d_w1T[idx] = g_w1[(i * 128 + j) * 64 + c];
    } else if (idx < 65536) {                    // w2T[i][j][o] = g_w2[i][o][j]
        int t = idx - 32768;
        int i = t >> 13, r = t & 8191, j = r >> 6, o = r & 63;
        d_w2T[t] = g_w2[(i * 64 + o) * 128 + j];
    } else if (idx < 81920) {                    // wwT[i][c][o] = w_w[i][o][c]
        int t = idx - 65536;
        int i = t >> 12, r = t & 4095, c = r >> 6, o = r & 63;
        d_wwT[t] = w_w[(i * 64 + o) * 64 + c];
    } else if (idx < 90112) {                    // fc1T[c][j] = fc1_w[j][c]
        int t = idx - 81920;
        int c = t >> 7, j = t & 127;
        d_fc1T[t] = fc1_w[j * 64 + c];
    }
}

__global__ void zero_tail_kernel() {
    int idx = blockIdx.x * 256 + threadIdx.x;    // 1024 rows x 256 tail cols
    int row = idx >> 8, col = NXV + (idx & 255);
    d_h[(size_t)row * XS + col] = 0.f;
}

// ------------------- fc0 -------------------
__global__ void __launch_bounds__(128) fc0_kernel(const float* __restrict__ xin,
                                                  const float* __restrict__ gin,
                                                  const float* __restrict__ w,
                                                  const float* __restrict__ bias) {
    __shared__ float sw[64 * 32];
    __shared__ float sb[64];
    int tid = threadIdx.x;
    for (int l = tid; l < 64 * 31; l += 128) {
        int wo = l / 31, c = l - wo * 31;
        sw[wo * 32 + c] = w[l];
    }
    if (tid < 64) sb[tid] = bias[tid];
    __syncthreads();
    int b = blockIdx.y;
    int x = blockIdx.x * 128 + tid;
    float rin[31];
    const float* xi = xin + ((size_t)b * NXV + x) * 30;
#pragma unroll
    for (int c = 0; c < 30; c++) rin[c] = __ldg(&xi[c]);
    rin[30] = __ldg(&gin[(size_t)b * NXV + x]);
    for (int wo = 0; wo < 64; wo++) {
        float acc = sb[wo];
#pragma unroll
        for (int c = 0; c < 31; c++) acc = fmaf(rin[c], sw[wo * 32 + c], acc);
        d_h[(size_t)(b * 64 + wo) * XS + x] = acc;
    }
}

// ------------------- 1x1 conv (cp.async double-buffered, f32x2) -------------------
// ACT: 0=none, 1=gelu, 2=scale by softplus(*alpha)
template<int CIN, int COUT, int ACT>
__global__ void __launch_bounds__(256, 2) conv1x1_kernel(
    const float* __restrict__ in,    // [b*CIN + c][XS]
    const float* __restrict__ wT,    // [CIN][COUT]
    const float* __restrict__ bias,  // [COUT]
    float* __restrict__ out,         // [b*COUT + o][XS]
    const float* __restrict__ alpha)
{
    constexpr int BP  = (COUT >= 128) ? 128 : 256;  // positions per block
    constexpr int TPp = BP / 32;                    // pos per thread (4/8)
    constexpr int TOc = COUT / 8;                   // outs per thread (16/8)
    constexpr int OP  = TOc / 2;                    // out pairs (8/4)
    constexpr int NTt = CIN / 16;
    constexpr int SIC = (16 * BP / 4) / 256;        // si chunks/thread
    constexpr int SWC = (16 * COUT / 4) / 256;      // swt chunks/thread
    __shared__ float si [2][16][BP];
    __shared__ float swt[2][16][COUT];
    const int b   = blockIdx.y;
    const int p0  = blockIdx.x * BP;
    const int tid = threadIdx.x;
    const int po  = (tid & 31) * TPp;
    const int oo  = (tid >> 5) * TOc;

    const float* inb = in + (size_t)b * CIN * XS + p0;

    uint64_t acc[TPp][OP];
#pragma unroll
    for (int p = 0; p < TPp; p++)
#pragma unroll
        for (int j = 0; j < OP; j++) acc[p][j] = 0ull;

    {
#pragma unroll
        for (int l = 0; l < SIC; l++) {
            int c = l * 256 + tid;
            int k = c / (BP / 4), q = (c % (BP / 4)) * 4;
            cp16(s2u(&si[0][k][q]), inb + k * XS + q);
        }
#pragma unroll
        for (int l = 0; l < SWC; l++) {
            int c = l * 256 + tid;
            int k = c / (COUT / 4), q = (c % (COUT / 4)) * 4;
            cp16(s2u(&swt[0][k][q]), wT + k * COUT + q);
        }
        CP_COMMIT;
    }
#pragma unroll
    for (int t = 0; t < NTt; t++) {
        const int buf = t & 1;
        if (t + 1 < NTt) {
            const int c0 = (t + 1) * 16;
#pragma unroll
            for (int l = 0; l < SIC; l++) {
                int c = l * 256 + tid;
                int k = c / (BP / 4), q = (c % (BP / 4)) * 4;
                cp16(s2u(&si[buf ^ 1][k][q]), inb + (c0 + k) * XS + q);
            }
#pragma unroll
            for (int l = 0; l < SWC; l++) {
                int c = l * 256 + tid;
                int k = c / (COUT / 4), q = (c % (COUT / 4)) * 4;
                cp16(s2u(&swt[buf ^ 1][k][q]), wT + (c0 + k) * COUT + q);
            }
            CP_COMMIT;
            CP_WAIT(1);
        } else {
            CP_WAIT(0);
        }
        __syncthreads();
#pragma unroll
        for (int k = 0; k < 16; k++) {
            uint64_t pa[TPp];
#pragma unroll
            for (int u = 0; u < TPp / 4; u++) {
                float4 av = *(const float4*)&si[buf][k][po + 4 * u];
                pa[4*u+0] = pack2(av.x, av.x);
                pa[4*u+1] = pack2(av.y, av.y);
                pa[4*u+2] = pack2(av.z, av.z);
                pa[4*u+3] = pack2(av.w, av.w);
            }
#pragma unroll
            for (int j = 0; j < OP; j++) {
                uint64_t wv = *(const uint64_t*)&swt[buf][k][oo + 2 * j];
#pragma unroll
                for (int p = 0; p < TPp; p++) FMA2(acc[p][j], wv, pa[p]);
            }
        }
        __syncthreads();
    }

    float scv = 1.f;
    if (ACT == 2) scv = softplus_(__ldg(alpha));
#pragma unroll
    for (int j = 0; j < OP; j++) {
        int o0 = oo + 2 * j;
        float b0 = __ldg(&bias[o0]);
        float b1 = __ldg(&bias[o0 + 1]);
        float vlo[TPp], vhi[TPp];
#pragma unroll
        for (int p = 0; p < TPp; p++) {
            unpack2(acc[p][j], vlo[p], vhi[p]);
            vlo[p] += b0; vhi[p] += b1;
            if (ACT == 1) { vlo[p] = gelu_(vlo[p]); vhi[p] = gelu_(vhi[p]); }
            if (ACT == 2) { vlo[p] *= scv; vhi[p] *= scv; }
        }
        float* r0 = out + ((size_t)b * COUT + o0) * XS + p0 + po;
        float* r1 = r0 + XS;
#pragma unroll
        for (int q = 0; q < TPp / 4; q++) {
            *(float4*)&r0[4*q] = make_float4(vlo[4*q], vlo[4*q+1], vlo[4*q+2], vlo[4*q+3]);
            *(float4*)&r1[4*q] = make_float4(vhi[4*q], vhi[4*q+1], vhi[4*q+2], vhi[4*q+3]);
        }
    }
}

// ------------------- forward DFT (R3 layout: split-K, [k][row+pad]) -------------------
__global__ void __launch_bounds__(256) fdft_kernel() {
    const int rt = blockIdx.x;     // 0..31 : 64-row tiles (16 h, 16 g)
    const int ks = blockIdx.y;     // 0..16 : K slices
    const float* src = (rt < 16) ? d_h + (size_t)rt * 64 * XS
                                 : d_g + (size_t)(rt - 16) * 64 * XS;
    const int kbase0 = ks * 1024;
    const int klen   = (ks == 16) ? 32 : 1024;

    __shared__ float sa[16][66];
    __shared__ float sb[16][128];
    const int tid = threadIdx.x;
    const int mo = (tid & 31) * 4;
    const int ro = (tid >> 5) * 8;

    uint64_t accp[4][4];           // [row-pair][mode], lanes = (row even, row odd)
#pragma unroll
    for (int r = 0; r < 4; r++)
#pragma unroll
        for (int p = 0; p < 4; p++) accp[r][p] = 0ull;

    for (int kk = 0; kk < klen; kk += 16) {
        const int kb = kbase0 + kk;
        __syncthreads();
#pragma unroll
        for (int l = 0; l < 4; l++) {
            int idx = l * 256 + tid;
            int r = idx >> 4, k = idx & 15;
            sa[k][r] = src[(size_t)r * XS + kb + k];
        }
#pragma unroll
        for (int l = 0; l < 8; l++) {
            int idx = l * 256 + tid;
            int k = idx >> 7, m = idx & 127;
            sb[k][m] = d_ftab[(size_t)(kb + k) * 128 + m];
        }
        __syncthreads();
#pragma unroll
        for (int k = 0; k < 16; k++) {
            float4 bv = *(const float4*)&sb[k][mo];
            uint64_t pb[4];
            pb[0] = pack2(bv.x, bv.x); pb[1] = pack2(bv.y, bv.y);
            pb[2] = pack2(bv.z, bv.z); pb[3] = pack2(bv.w, bv.w);
#pragma unroll
            for (int r2 = 0; r2 < 4; r2++) {
                uint64_t a2 = *(const uint64_t*)&sa[k][ro + 2 * r2];
#pragma unroll
                for (int p = 0; p < 4; p++) FMA2(accp[r2][p], a2, pb[p]);
            }
        }
    }
#pragma unroll
    for (int r2 = 0; r2 < 4; r2++) {
        float4 vlo, vhi;
        unpack2(accp[r2][0], vlo.x, vhi.x);
        unpack2(accp[r2][1], vlo.y, vhi.y);
        unpack2(accp[r2][2], vlo.z, vhi.z);
        unpack2(accp[r2][3], vlo.w, vhi.w);
        *(float4*)&d_part[((size_t)ks * 2048 + rt * 64 + ro + 2 * r2) * 128 + mo]     = vlo;
        *(float4*)&d_part[((size_t)ks * 2048 + rt * 64 + ro + 2 * r2 + 1) * 128 + mo] = vhi;
    }
}

__global__ void reduce_kernel() {
    int idx = blockIdx.x * 256 + threadIdx.x;   // 262144
    float s = 0.f;
#pragma unroll
    for (int k = 0; k < 17; k++) s += d_part[(size_t)k * 262144 + idx];
    d_fw[idx] = s;
}

// ------------------- mode mix + ETD coefficients -------------------
__global__ void __launch_bounds__(512) modemix_kernel(const float* __restrict__ mix_re,
                                                      const float* __restrict__ mix_im,
                                                      const float* __restrict__ log_decay,
                                                      int blk) {
    __shared__ float sg[64 * 128];
    const int b  = blockIdx.x;
    const int og = blockIdx.y;
    const int tid = threadIdx.x;
#pragma unroll
    for (int l = 0; l < 16; l++) {
        int idx = l * 512 + tid;
        sg[idx] = d_fw[(size_t)(1024 + b * 64) * 128 + idx];
    }
    __syncthreads();
    const int m = tid & 63, ol = tid >> 6;
    const int o = og * 8 + ol;
    const float* mr = mix_re + (size_t)blk * 262144 + o * 64 + m;
    const float* mi = mix_im + (size_t)blk * 262144 + o * 64 + m;
    float ar = 0.f, ai = 0.f;
#pragma unroll 4
    for (int i = 0; i < 64; i++) {
        float2 gh = *(const float2*)&sg[i * 128 + 2 * m];
        float r_ = __ldg(&mr[(size_t)i * 4096]);
        float i_ = __ldg(&mi[(size_t)i * 4096]);
        ar = fmaf(gh.x, r_, ar); ar = fmaf(-gh.y, i_, ar);
        ai = fmaf(gh.x, i_, ai); ai = fmaf( gh.y, r_, ai);
    }
    float ld = __ldg(&log_decay[((size_t)blk * 64 + o) * 64 + m]);
    float z  = -softplus_(ld);
    float ez = expf(z);
    float phi = (fabsf(z) < 1e-6f) ? (1.f + 0.5f * z + z * z * (1.f / 6.f))
                                   : (expm1f(z) / z);
    float gq = (float)m * (1.f / 63.f);
    float r2 = gq * gq + 1e-12f;
    float r8 = r2 * r2; r8 = r8 * r8;
    float pf = phi * expf(-2.f * r8);

    size_t vrow = ((size_t)b * 64 + o) * 128;
    float vr = d_fw[vrow + 2 * m], vi = d_fw[vrow + 2 * m + 1];
    float outr = fmaf(ez, vr, pf * ar);
    float outi = fmaf(ez, vi, pf * ai);
    const float inv = 1.0f / 16386.0f;
    d_outm[vrow + 2 * m]     = (m == 0) ? outr * inv : 2.f * outr * inv;
    d_outm[vrow + 2 * m + 1] = (m == 0) ? 0.f        : -2.f * outi * inv;
}

// ------------------- inverse DFT + skip + activation (R3, in-place h) -------------------
__global__ void __launch_bounds__(256) idft_kernel(const float* __restrict__ alpha_w, int act) {
    const int x0   = blockIdx.x * 128;
    const int row0 = blockIdx.y * 64;
    __shared__ float sc_[16][66];
    __shared__ float st [16][128];
    const int tid = threadIdx.x;
    const int xo = (tid & 31) * 4;
    const int ro = (tid >> 5) * 8;

    uint64_t accp[4][4];           // [row-pair][x], lanes = (row even, row odd)
#pragma unroll
    for (int r = 0; r < 4; r++)
#pragma unroll
        for (int p = 0; p < 4; p++) accp[r][p] = 0ull;

    for (int kb = 0; kb < 128; kb += 16) {
        __syncthreads();
#pragma unroll
        for (int l = 0; l < 4; l++) {
            int idx = l * 256 + tid;
            int r = idx >> 4, k = idx & 15;
            sc_[k][r] = d_outm[(size_t)(row0 + r) * 128 + kb + k];
        }
#pragma unroll
        for (int l = 0; l < 8; l++) {
            int idx = l * 256 + tid;
            int k = idx >> 7, xl = idx & 127;
            st[k][xl] = d_itab[(size_t)(kb + k) * XS + x0 + xl];
        }
        __syncthreads();
#pragma unroll
        for (int k = 0; k < 16; k++) {
            float4 tv = *(const float4*)&st[k][xo];
            uint64_t pt[4];
            pt[0] = pack2(tv.x, tv.x); pt[1] = pack2(tv.y, tv.y);
            pt[2] = pack2(tv.z, tv.z); pt[3] = pack2(tv.w, tv.w);
#pragma unroll
            for (int r2 = 0; r2 < 4; r2++) {
                uint64_t c2 = *(const uint64_t*)&sc_[k][ro + 2 * r2];
#pragma unroll
                for (int p = 0; p < 4; p++) FMA2(accp[r2][p], c2, pt[p]);
            }
        }
    }
    const float aw = softplus_(__ldg(alpha_w));
#pragma unroll
    for (int r2 = 0; r2 < 4; r2++) {
        float4 vlo, vhi;
        unpack2(accp[r2][0], vlo.x, vhi.x);
        unpack2(accp[r2][1], vlo.y, vhi.y);
        unpack2(accp[r2][2], vlo.z, vhi.z);
        unpack2(accp[r2][3], vlo.w, vhi.w);
        size_t off0 = (size_t)(row0 + ro + 2 * r2) * XS + x0 + xo;
        size_t off1 = off0 + XS;
        float4 w0 = *(const float4*)&d_wout[off0];
        float4 w1 = *(const float4*)&d_wout[off1];
        vlo.x = fmaf(aw, w0.x, vlo.x); vlo.y = fmaf(aw, w0.y, vlo.y);
        vlo.z = fmaf(aw, w0.z, vlo.z); vlo.w = fmaf(aw, w0.w, vlo.w);
        vhi.x = fmaf(aw, w1.x, vhi.x); vhi.y = fmaf(aw, w1.y, vhi.y);
        vhi.z = fmaf(aw, w1.z, vhi.z); vhi.w = fmaf(aw, w1.w, vhi.w);
        if (act) {
            vlo.x = gelu_(vlo.x); vlo.y = gelu_(vlo.y); vlo.z = gelu_(vlo.z); vlo.w = gelu_(vlo.w);
            vhi.x = gelu_(vhi.x); vhi.y = gelu_(vhi.y); vhi.z = gelu_(vhi.z); vhi.w = gelu_(vhi.w);
        }
        *(float4*)&d_h[off0] = vlo;
        *(float4*)&d_h[off1] = vhi;
    }
}

// ------------------- fc2 -------------------
__global__ void __launch_bounds__(128) fc2_kernel(const float* __restrict__ w,
                                                  const float* __restrict__ bias,
                                                  float* __restrict__ out) {
    __shared__ float sw[3][128];
    int tid = threadIdx.x;
    for (int l = tid; l < 384; l += 128) sw[l >> 7][l & 127] = w[l];
    __syncthreads();
    int b = blockIdx.y;
    int x = blockIdx.x * 128 + tid;
    float a0 = __ldg(&bias[0]), a1 = __ldg(&bias[1]), a2 = __ldg(&bias[2]);
#pragma unroll 4
    for (int j = 0; j < 128; j++) {
        float v = d_gmid[((size_t)b * 128 + j) * XS + x];
        a0 = fmaf(v, sw[0][j], a0);
        a1 = fmaf(v, sw[1][j], a1);
        a2 = fmaf(v, sw[2][j], a2);
    }
    size_t o = ((size_t)b * NXV + x) * 3;
    out[o] = a0; out[o + 1] = a1; out[o + 2] = a2;
}

// ------------------- launch -------------------
extern "C" void kernel_launch(void* const* d_in, const int* in_sizes, int n_in,
                              void* d_out, int out_size) {
    const float* x_in   = (const float*)d_in[0];
    const float* grid   = (const float*)d_in[1];
    const float* fc0_w  = (const float*)d_in[2];
    const float* fc0_b  = (const float*)d_in[3];
    const float* fc1_w  = (const float*)d_in[4];
    const float* fc1_b  = (const float*)d_in[5];
    const float* fc2_w  = (const float*)d_in[6];
    const float* fc2_b  = (const float*)d_in[7];
    const float* g_w1   = (const float*)d_in[8];
    const float* g_b1   = (const float*)d_in[9];
    const float* g_w2   = (const float*)d_in[10];
    const float* g_b2   = (const float*)d_in[11];
    const float* w_w    = (const float*)d_in[12];
    const float* w_b    = (const float*)d_in[13];
    const float* ldcy   = (const float*)d_in[14];
    const float* mix_re = (const float*)d_in[15];
    const float* mix_im = (const float*)d_in[16];
    const float* aw     = (const float*)d_in[17];
    const float* ag     = (const float*)d_in[18];

    float *ph, *pg, *pgmid, *pwout, *pw1T, *pw2T, *pwwT, *pfc1T;
    cudaGetSymbolAddress((void**)&ph,    d_h);
    cudaGetSymbolAddress((void**)&pg,    d_g);
    cudaGetSymbolAddress((void**)&pgmid, d_gmid);
    cudaGetSymbolAddress((void**)&pwout, d_wout);
    cudaGetSymbolAddress((void**)&pw1T,  d_w1T);
    cudaGetSymbolAddress((void**)&pw2T,  d_w2T);
    cudaGetSymbolAddress((void**)&pwwT,  d_wwT);
    cudaGetSymbolAddress((void**)&pfc1T, d_fc1T);

    fc0_kernel<<<dim3(128, 16), 128>>>(x_in, grid, fc0_w, fc0_b);
    zero_tail_kernel<<<1024, 256>>>();
    prep_weights_kernel<<<352, 256>>>(g_w1, g_w2, w_w, fc1_w);

    for (int i = 0; i < 4; i++) {
        conv1x1_kernel<64, 128, 1><<<dim3(130, 16), 256>>>(
            ph, pw1T + i * 8192, g_b1 + i * 128, pgmid, nullptr);
        if (i == 0) {
            init_ftab_kernel<<<(KPAD * 128 + 255) / 256, 256>>>();
            init_itab_kernel<<<(128 * XS + 255) / 256, 256>>>();
        }
        conv1x1_kernel<128, 64, 2><<<dim3(65, 16), 256>>>(
            pgmid, pw2T + i * 8192, g_b2 + i * 64, pg, ag);
        conv1x1_kernel<64, 64, 0><<<dim3(65, 16), 256>>>(
            ph, pwwT + i * 4096, w_b + i * 64, pwout, nullptr);
        fdft_kernel<<<dim3(32, 17), 256>>>();
        reduce_kernel<<<1024, 256>>>();
        modemix_kernel<<<dim3(16, 8), 512>>>(mix_re, mix_im, ldcy, i);
        idft_kernel<<<dim3(130, 16), 256>>>(aw, (i < 3) ? 1 : 0);
    }

    conv1x1_kernel<64, 128, 1><<<dim3(128, 16), 256>>>(
        ph, pfc1T, fc1_b, pgmid, nullptr);
    fc2_kernel<<<dim3(128, 16), 128>>>(fc2_w, fc2_b, (float*)d_out);
}

// round 7
// speedup vs baseline: 1.8382x; 1.0200x over previous
#include <cuda_runtime.h>
#include <math.h>
#include <stdint.h>

#define XP    16386
#define XS    16640          // row stride (65*256)
#define NXV   16384
#define KPAD  16416          // forward-DFT K extent (18*912)
#define NB    16

// ------------------- static device buffers -------------------
__device__ float d_h   [(size_t)NB * 64 * XS];
__device__ float d_g   [(size_t)NB * 64 * XS];
__device__ float d_gmid[(size_t)NB * 128 * XS];
__device__ float d_ftab[(size_t)KPAD * 128];      // [x][2m]=cos, [2m+1]=-sin
__device__ float d_itab[(size_t)128 * XS];        // [2m][x]=cos, [2m+1][x]=sin
__device__ float d_part[(size_t)18 * 2048 * 128];
__device__ float d_fw  [2048 * 128];
__device__ float d_outm[1024 * 128];
__device__ float d_coefW[64 * 64];                // aw * W for current block
__device__ float d_w1T [4 * 64 * 128];
__device__ float d_w2T [4 * 128 * 64];
__device__ float d_fc1T[64 * 128];

// ------------------- f32x2 packed helpers -------------------
__device__ __forceinline__ uint64_t pack2(float lo, float hi) {
    uint64_t r;
    asm("mov.b64 %0, {%1, %2};" : "=l"(r) : "f"(lo), "f"(hi));
    return r;
}
__device__ __forceinline__ void unpack2(uint64_t v, float& lo, float& hi) {
    asm("mov.b64 {%0, %1}, %2;" : "=f"(lo), "=f"(hi) : "l"(v));
}
#define FMA2(d, a, b) \
    asm("fma.rn.f32x2 %0, %1, %2, %0;" : "+l"(d) : "l"(a), "l"(b))

__device__ __forceinline__ uint32_t s2u(const void* p) {
    return (uint32_t)__cvta_generic_to_shared(p);
}
__device__ __forceinline__ void cp16(uint32_t s, const float* g) {
    asm volatile("cp.async.cg.shared.global [%0], [%1], 16;"
                 :: "r"(s), "l"(__cvta_generic_to_global(g)));
}
#define CP_COMMIT asm volatile("cp.async.commit_group;")
#define CP_WAIT(n) asm volatile("cp.async.wait_group %0;" :: "n"(n))

__device__ __forceinline__ float softplus_(float x) {
    return (x > 20.f) ? x : log1pf(expf(x));
}
__device__ __forceinline__ float gelu_(float v) {
    return 0.5f * v * (1.0f + erff(v * 0.70710678118654752f));
}

// ------------------- table init -------------------
__global__ void init_ftab_kernel() {
    int idx = blockIdx.x * 256 + threadIdx.x;
    if (idx >= KPAD * 128) return;
    int x = idx >> 7, t = idx & 127, m = t >> 1;
    float v = 0.f;
    if (x < XP) {
        int u = (x * m) % XP;
        float s, c;
        sincospif(2.0f * (float)u / (float)XP, &s, &c);
        v = (t & 1) ? -s : c;
    }
    d_ftab[idx] = v;
}

__global__ void init_itab_kernel() {
    int idx = blockIdx.x * 256 + threadIdx.x;
    if (idx >= 128 * XS) return;
    int t = idx / XS, x = idx - t * XS, m = t >> 1;
    float v = 0.f;
    if (x < XP) {
        int u = (x * m) % XP;
        float s, c;
        sincospif(2.0f * (float)u / (float)XP, &s, &c);
        v = (t & 1) ? s : c;
    }
    d_itab[idx] = v;
}

// ------------------- weight transposes -------------------
__global__ void prep_weights_kernel(const float* __restrict__ g_w1,
                                    const float* __restrict__ g_w2,
                                    const float* __restrict__ fc1_w) {
    int idx = blockIdx.x * 256 + threadIdx.x;
    if (idx < 32768) {
        int i = idx >> 13, r = idx & 8191, c = r >> 7, j = r & 127;
        d_w1T[idx] = g_w1[(i * 128 + j) * 64 + c];
    } else if (idx < 65536) {
        int t = idx - 32768;
        int i = t >> 13, r = t & 8191, j = r >> 6, o = r & 63;
        d_w2T[t] = g_w2[(i * 64 + o) * 128 + j];
    } else if (idx < 73728) {
        int t = idx - 65536;
        int c = t >> 7, j = t & 127;
        d_fc1T[t] = fc1_w[j * 64 + c];
    }
}

__global__ void zero_tail_kernel() {
    int idx = blockIdx.x * 256 + threadIdx.x;    // 1024 rows x 256 tail cols
    int row = idx >> 8, col = NXV + (idx & 255);
    d_h[(size_t)row * XS + col] = 0.f;
}

__global__ void coefw_kernel(const float* __restrict__ w_w,
                             const float* __restrict__ alpha_w, int blk) {
    int i = blockIdx.x * 256 + threadIdx.x;      // 4096
    d_coefW[i] = softplus_(__ldg(alpha_w)) * __ldg(&w_w[blk * 4096 + i]);
}

// ------------------- fc0 -------------------
__global__ void __launch_bounds__(128) fc0_kernel(const float* __restrict__ xin,
                                                  const float* __restrict__ gin,
                                                  const float* __restrict__ w,
                                                  const float* __restrict__ bias) {
    __shared__ float sw[64 * 32];
    __shared__ float sb[64];
    int tid = threadIdx.x;
    for (int l = tid; l < 64 * 31; l += 128) {
        int wo = l / 31, c = l - wo * 31;
        sw[wo * 32 + c] = w[l];
    }
    if (tid < 64) sb[tid] = bias[tid];
    __syncthreads();
    int b = blockIdx.y;
    int x = blockIdx.x * 128 + tid;
    float rin[31];
    const float* xi = xin + ((size_t)b * NXV + x) * 30;
#pragma unroll
    for (int c = 0; c < 30; c++) rin[c] = __ldg(&xi[c]);
    rin[30] = __ldg(&gin[(size_t)b * NXV + x]);
    for (int wo = 0; wo < 64; wo++) {
        float acc = sb[wo];
#pragma unroll
        for (int c = 0; c < 31; c++) acc = fmaf(rin[c], sw[wo * 32 + c], acc);
        d_h[(size_t)(b * 64 + wo) * XS + x] = acc;
    }
}

// ------------------- 1x1 conv (cp.async double-buffered, f32x2) -------------------
// ACT: 0=none, 1=gelu, 2=scale by softplus(*alpha)
template<int CIN, int COUT, int ACT>
__global__ void __launch_bounds__(256, 2) conv1x1_kernel(
    const float* __restrict__ in,    // [b*CIN + c][XS]
    const float* __restrict__ wT,    // [CIN][COUT]
    const float* __restrict__ bias,  // [COUT]
    float* __restrict__ out,         // [b*COUT + o][XS]
    const float* __restrict__ alpha)
{
    constexpr int BP  = (COUT >= 128) ? 128 : 256;
    constexpr int TPp = BP / 32;
    constexpr int TOc = COUT / 8;
    constexpr int OP  = TOc / 2;
    constexpr int NTt = CIN / 16;
    constexpr int SIC = (16 * BP / 4) / 256;
    constexpr int SWC = (16 * COUT / 4) / 256;
    __shared__ float si [2][16][BP];
    __shared__ float swt[2][16][COUT];
    const int b   = blockIdx.y;
    const int p0  = blockIdx.x * BP;
    const int tid = threadIdx.x;
    const int po  = (tid & 31) * TPp;
    const int oo  = (tid >> 5) * TOc;

    const float* inb = in + (size_t)b * CIN * XS + p0;

    uint64_t acc[TPp][OP];
#pragma unroll
    for (int p = 0; p < TPp; p++)
#pragma unroll
        for (int j = 0; j < OP; j++) acc[p][j] = 0ull;

    {
#pragma unroll
        for (int l = 0; l < SIC; l++) {
            int c = l * 256 + tid;
            int k = c / (BP / 4), q = (c % (BP / 4)) * 4;
            cp16(s2u(&si[0][k][q]), inb + k * XS + q);
        }
#pragma unroll
        for (int l = 0; l < SWC; l++) {
            int c = l * 256 + tid;
            int k = c / (COUT / 4), q = (c % (COUT / 4)) * 4;
            cp16(s2u(&swt[0][k][q]), wT + k * COUT + q);
        }
        CP_COMMIT;
    }
#pragma unroll
    for (int t = 0; t < NTt; t++) {
        const int buf = t & 1;
        if (t + 1 < NTt) {
            const int c0 = (t + 1) * 16;
#pragma unroll
            for (int l = 0; l < SIC; l++) {
                int c = l * 256 + tid;
                int k = c / (BP / 4), q = (c % (BP / 4)) * 4;
                cp16(s2u(&si[buf ^ 1][k][q]), inb + (c0 + k) * XS + q);
            }
#pragma unroll
            for (int l = 0; l < SWC; l++) {
                int c = l * 256 + tid;
                int k = c / (COUT / 4), q = (c % (COUT / 4)) * 4;
                cp16(s2u(&swt[buf ^ 1][k][q]), wT + (c0 + k) * COUT + q);
            }
            CP_COMMIT;
            CP_WAIT(1);
        } else {
            CP_WAIT(0);
        }
        __syncthreads();
#pragma unroll
        for (int k = 0; k < 16; k++) {
            uint64_t pa[TPp];
#pragma unroll
            for (int u = 0; u < TPp / 4; u++) {
                float4 av = *(const float4*)&si[buf][k][po + 4 * u];
                pa[4*u+0] = pack2(av.x, av.x);
                pa[4*u+1] = pack2(av.y, av.y);
                pa[4*u+2] = pack2(av.z, av.z);
                pa[4*u+3] = pack2(av.w, av.w);
            }
#pragma unroll
            for (int j = 0; j < OP; j++) {
                uint64_t wv = *(const uint64_t*)&swt[buf][k][oo + 2 * j];
#pragma unroll
                for (int p = 0; p < TPp; p++) FMA2(acc[p][j], wv, pa[p]);
            }
        }
        __syncthreads();
    }

    float scv = 1.f;
    if (ACT == 2) scv = softplus_(__ldg(alpha));
#pragma unroll
    for (int j = 0; j < OP; j++) {
        int o0 = oo + 2 * j;
        float b0 = __ldg(&bias[o0]);
        float b1 = __ldg(&bias[o0 + 1]);
        float vlo[TPp], vhi[TPp];
#pragma unroll
        for (int p = 0; p < TPp; p++) {
            unpack2(acc[p][j], vlo[p], vhi[p]);
            vlo[p] += b0; vhi[p] += b1;
            if (ACT == 1) { vlo[p] = gelu_(vlo[p]); vhi[p] = gelu_(vhi[p]); }
            if (ACT == 2) { vlo[p] *= scv; vhi[p] *= scv; }
        }
        float* r0 = out + ((size_t)b * COUT + o0) * XS + p0 + po;
        float* r1 = r0 + XS;
#pragma unroll
        for (int q = 0; q < TPp / 4; q++) {
            *(float4*)&r0[4*q] = make_float4(vlo[4*q], vlo[4*q+1], vlo[4*q+2], vlo[4*q+3]);
            *(float4*)&r1[4*q] = make_float4(vhi[4*q], vhi[4*q+1], vhi[4*q+2], vhi[4*q+3]);
        }
    }
}

// ------------------- forward DFT (dup-broadcast rows, 18 balanced splits) -------------------
__global__ void __launch_bounds__(256, 2) fdft_kernel() {
    const int rt = blockIdx.x;     // 0..15 : 128-row tiles (8 h, 8 g)
    const int ks = blockIdx.y;     // 0..17 : K splits of 912 (57 tiles)
    const float* src = (rt < 8) ? d_h + (size_t)rt * 128 * XS
                                : d_g + (size_t)(rt - 8) * 128 * XS;
    const int kbase = ks * 912;

    __shared__ float sa[2][16][260];   // rows DUPLICATED: [k][2*row], pad->260
    __shared__ float sf[2][16][128];   // ftab straight [k][comp]
    const int tid = threadIdx.x;
    const int cg = tid & 15;           // comp group: comps {4cg..4cg+3, 64+4cg..}
    const int rg = tid >> 4;           // row group: rows rg*8..rg*8+7

    uint64_t acc[8][4];
#pragma unroll
    for (int r = 0; r < 8; r++)
#pragma unroll
        for (int j = 0; j < 4; j++) acc[r][j] = 0ull;

    float  ra[8];
    float4 rf[2];
    // prefetch tile 0
#pragma unroll
    for (int l = 0; l < 8; l++) {
        int c = l * 256 + tid;
        ra[l] = src[(size_t)(c >> 4) * XS + kbase + (c & 15)];
    }
#pragma unroll
    for (int l = 0; l < 2; l++) {
        int c = l * 256 + tid;
        rf[l] = *(const float4*)&d_ftab[(size_t)(kbase + (c >> 5)) * 128 + (c & 31) * 4];
    }
#pragma unroll
    for (int l = 0; l < 8; l++) {
        int c = l * 256 + tid;
        *(uint64_t*)&sa[0][c & 15][2 * (c >> 4)] = pack2(ra[l], ra[l]);
    }
#pragma unroll
    for (int l = 0; l < 2; l++) {
        int c = l * 256 + tid;
        *(float4*)&sf[0][c >> 5][(c & 31) * 4] = rf[l];
    }
    __syncthreads();

    for (int t = 0; t < 57; t++) {
        const int buf = t & 1;
        if (t < 56) {
            const int kb = kbase + (t + 1) * 16;
#pragma unroll
            for (int l = 0; l < 8; l++) {
                int c = l * 256 + tid;
                ra[l] = src[(size_t)(c >> 4) * XS + kb + (c & 15)];
            }
#pragma unroll
            for (int l = 0; l < 2; l++) {
                int c = l * 256 + tid;
                rf[l] = *(const float4*)&d_ftab[(size_t)(kb + (c >> 5)) * 128 + (c & 31) * 4];
            }
        }
#pragma unroll
        for (int k = 0; k < 16; k++) {
            ulonglong2 c0 = *(const ulonglong2*)&sf[buf][k][cg * 4];
            ulonglong2 c1 = *(const ulonglong2*)&sf[buf][k][64 + cg * 4];
            ulonglong2 r01 = *(const ulonglong2*)&sa[buf][k][rg * 16];
            ulonglong2 r23 = *(const ulonglong2*)&sa[buf][k][rg * 16 + 4];
            ulonglong2 r45 = *(const ulonglong2*)&sa[buf][k][rg * 16 + 8];
            ulonglong2 r67 = *(const ulonglong2*)&sa[buf][k][rg * 16 + 12];
            uint64_t rd[8] = {r01.x, r01.y, r23.x, r23.y, r45.x, r45.y, r67.x, r67.y};
#pragma unroll
            for (int r = 0; r < 8; r++) {
                FMA2(acc[r][0], rd[r], c0.x);
                FMA2(acc[r][1], rd[r], c0.y);
                FMA2(acc[r][2], rd[r], c1.x);
                FMA2(acc[r][3], rd[r], c1.y);
            }
        }
        if (t < 56) {
#pragma unroll
            for (int l = 0; l < 8; l++) {
                int c = l * 256 + tid;
                *(uint64_t*)&sa[buf ^ 1][c & 15][2 * (c >> 4)] = pack2(ra[l], ra[l]);
            }
#pragma unroll
            for (int l = 0; l < 2; l++) {
                int c = l * 256 + tid;
                *(float4*)&sf[buf ^ 1][c >> 5][(c & 31) * 4] = rf[l];
            }
        }
        __syncthreads();
    }
#pragma unroll
    for (int r = 0; r < 8; r++) {
        int row = rt * 128 + rg * 8 + r;
        float4 v0, v1;
        unpack2(acc[r][0], v0.x, v0.y);
        unpack2(acc[r][1], v0.z, v0.w);
        unpack2(acc[r][2], v1.x, v1.y);
        unpack2(acc[r][3], v1.z, v1.w);
        float* pp = &d_part[((size_t)ks * 2048 + row) * 128];
        *(float4*)&pp[cg * 4]      = v0;
        *(float4*)&pp[64 + cg * 4] = v1;
    }
}

__global__ void reduce_kernel() {
    int idx = blockIdx.x * 256 + threadIdx.x;   // 262144
    float s = 0.f;
#pragma unroll
    for (int k = 0; k < 18; k++) s += d_part[(size_t)k * 262144 + idx];
    d_fw[idx] = s;
}

// ------------------- mode mix + ETD coefficients (bias folded at m=0) -------------------
__global__ void __launch_bounds__(512) modemix_kernel(const float* __restrict__ mix_re,
                                                      const float* __restrict__ mix_im,
                                                      const float* __restrict__ log_decay,
                                                      const float* __restrict__ w_b,
                                                      const float* __restrict__ alpha_w,
                                                      int blk) {
    __shared__ float sg[64 * 128];
    const int b  = blockIdx.x;
    const int og = blockIdx.y;
    const int tid = threadIdx.x;
#pragma unroll
    for (int l = 0; l < 16; l++) {
        int idx = l * 512 + tid;
        sg[idx] = d_fw[(size_t)(1024 + b * 64) * 128 + idx];
    }
    __syncthreads();
    const int m = tid & 63, ol = tid >> 6;
    const int o = og * 8 + ol;
    const float* mr = mix_re + (size_t)blk * 262144 + o * 64 + m;
    const float* mi = mix_im + (size_t)blk * 262144 + o * 64 + m;
    float ar = 0.f, ai = 0.f;
#pragma unroll 4
    for (int i = 0; i < 64; i++) {
        float2 gh = *(const float2*)&sg[i * 128 + 2 * m];
        float r_ = __ldg(&mr[(size_t)i * 4096]);
        float i_ = __ldg(&mi[(size_t)i * 4096]);
        ar = fmaf(gh.x, r_, ar); ar = fmaf(-gh.y, i_, ar);
        ai = fmaf(gh.x, i_, ai); ai = fmaf( gh.y, r_, ai);
    }
    float ld = __ldg(&log_decay[((size_t)blk * 64 + o) * 64 + m]);
    float z  = -softplus_(ld);
    float ez = expf(z);
    float phi = (fabsf(z) < 1e-6f) ? (1.f + 0.5f * z + z * z * (1.f / 6.f))
                                   : (expm1f(z) / z);
    float gq = (float)m * (1.f / 63.f);
    float r2 = gq * gq + 1e-12f;
    float r8 = r2 * r2; r8 = r8 * r8;
    float pf = phi * expf(-2.f * r8);

    size_t vrow = ((size_t)b * 64 + o) * 128;
    float vr = d_fw[vrow + 2 * m], vi = d_fw[vrow + 2 * m + 1];
    float outr = fmaf(ez, vr, pf * ar);
    float outi = fmaf(ez, vi, pf * ai);
    const float inv = 1.0f / 16386.0f;
    float resr = (m == 0) ? outr * inv : 2.f * outr * inv;
    if (m == 0) resr += softplus_(__ldg(alpha_w)) * __ldg(&w_b[blk * 64 + o]);
    d_outm[vrow + 2 * m]     = resr;
    d_outm[vrow + 2 * m + 1] = (m == 0) ? 0.f : -2.f * outi * inv;
}

// ---- inverse DFT + fused w-skip + activation (K=192 dup-broadcast, in-place h) ----
__global__ void __launch_bounds__(256, 2) idft_kernel(int act) {
    const int x0 = blockIdx.x * 256;
    const int b  = blockIdx.y;
    __shared__ float st[2][16][256];   // straight [k][x]
    __shared__ float sc[2][16][136];   // coef DUP [k][2*row], pad->136
    const int tid = threadIdx.x;
    const int xg = tid & 15;           // x chunks: {c*64 + xg*4 .. +3}, c=0..3
    const int rg = tid >> 4;           // rows rg*4..rg*4+3
    float* hb = d_h + (size_t)b * 64 * XS;

    uint64_t acc[4][8];
#pragma unroll
    for (int r = 0; r < 4; r++)
#pragma unroll
        for (int j = 0; j < 8; j++) acc[r][j] = 0ull;

    float4 rt4[4];
    float  rc[4];
    // prefetch tile 0 (itab k=0..15)
#pragma unroll
    for (int l = 0; l < 4; l++) {
        int c = l * 256 + tid;
        rt4[l] = *(const float4*)&d_itab[(size_t)(c >> 6) * XS + x0 + (c & 63) * 4];
    }
#pragma unroll
    for (int l = 0; l < 4; l++) {
        int c = l * 256 + tid;
        rc[l] = d_outm[(size_t)(b * 64 + (c >> 4)) * 128 + (c & 15)];
    }
#pragma unroll
    for (int l = 0; l < 4; l++) {
        int c = l * 256 + tid;
        *(float4*)&st[0][c >> 6][(c & 63) * 4] = rt4[l];
    }
#pragma unroll
    for (int l = 0; l < 4; l++) {
        int c = l * 256 + tid;
        *(uint64_t*)&sc[0][c & 15][2 * (c >> 4)] = pack2(rc[l], rc[l]);
    }
    __syncthreads();

#pragma unroll
    for (int t = 0; t < 12; t++) {
        const int buf = t & 1;
        if (t < 11) {
            const int kb = (t + 1) * 16;
#pragma unroll
            for (int l = 0; l < 4; l++) {
                int c = l * 256 + tid;
                int k = c >> 6, q = (c & 63) * 4;
                const float* gsrc = (kb < 128)
                    ? &d_itab[(size_t)(kb + k) * XS + x0 + q]
                    : &hb[(size_t)(kb - 128 + k) * XS + x0 + q];
                rt4[l] = *(const float4*)gsrc;
            }
#pragma unroll
            for (int l = 0; l < 4; l++) {
                int c = l * 256 + tid;
                int k = c & 15, row = c >> 4;
                rc[l] = (kb < 128)
                    ? d_outm[(size_t)(b * 64 + row) * 128 + kb + k]
                    : d_coefW[row * 64 + (kb - 128) + k];
            }
        }
#pragma unroll
        for (int k = 0; k < 16; k++) {
            ulonglong2 w01 = *(const ulonglong2*)&sc[buf][k][rg * 8];
            ulonglong2 w23 = *(const ulonglong2*)&sc[buf][k][rg * 8 + 4];
            uint64_t wd[4] = {w01.x, w01.y, w23.x, w23.y};
#pragma unroll
            for (int c = 0; c < 4; c++) {
                ulonglong2 xv = *(const ulonglong2*)&st[buf][k][c * 64 + xg * 4];
#pragma unroll
                for (int r = 0; r < 4; r++) {
                    FMA2(acc[r][2 * c],     wd[r], xv.x);
                    FMA2(acc[r][2 * c + 1], wd[r], xv.y);
                }
            }
        }
        if (t < 11) {
#pragma unroll
            for (int l = 0; l < 4; l++) {
                int c = l * 256 + tid;
                *(float4*)&st[buf ^ 1][c >> 6][(c & 63) * 4] = rt4[l];
            }
#pragma unroll
            for (int l = 0; l < 4; l++) {
                int c = l * 256 + tid;
                *(uint64_t*)&sc[buf ^ 1][c & 15][2 * (c >> 4)] = pack2(rc[l], rc[l]);
            }
        }
        __syncthreads();
    }
#pragma unroll
    for (int r = 0; r < 4; r++) {
        int row = rg * 4 + r;
#pragma unroll
        for (int c = 0; c < 4; c++) {
            float4 v;
            unpack2(acc[r][2 * c],     v.x, v.y);
            unpack2(acc[r][2 * c + 1], v.z, v.w);
            if (act) { v.x = gelu_(v.x); v.y = gelu_(v.y); v.z = gelu_(v.z); v.w = gelu_(v.w); }
            *(float4*)&hb[(size_t)row * XS + x0 + c * 64 + xg * 4] = v;
        }
    }
}

// ------------------- fc2 -------------------
__global__ void __launch_bounds__(128) fc2_kernel(const float* __restrict__ w,
                                                  const float* __restrict__ bias,
                                                  float* __restrict__ out) {
    __shared__ float sw[3][128];
    int tid = threadIdx.x;
    for (int l = tid; l < 384; l += 128) sw[l >> 7][l & 127] = w[l];
    __syncthreads();
    int b = blockIdx.y;
    int x = blockIdx.x * 128 + tid;
    float a0 = __ldg(&bias[0]), a1 = __ldg(&bias[1]), a2 = __ldg(&bias[2]);
#pragma unroll 4
    for (int j = 0; j < 128; j++) {
        float v = d_gmid[((size_t)b * 128 + j) * XS + x];
        a0 = fmaf(v, sw[0][j], a0);
        a1 = fmaf(v, sw[1][j], a1);
        a2 = fmaf(v, sw[2][j], a2);
    }
    size_t o = ((size_t)b * NXV + x) * 3;
    out[o] = a0; out[o + 1] = a1; out[o + 2] = a2;
}

// ------------------- launch -------------------
extern "C" void kernel_launch(void* const* d_in, const int* in_sizes, int n_in,
                              void* d_out, int out_size) {
    const float* x_in   = (const float*)d_in[0];
    const float* grid   = (const float*)d_in[1];
    const float* fc0_w  = (const float*)d_in[2];
    const float* fc0_b  = (const float*)d_in[3];
    const float* fc1_w  = (const float*)d_in[4];
    const float* fc1_b  = (const float*)d_in[5];
    const float* fc2_w  = (const float*)d_in[6];
    const float* fc2_b  = (const float*)d_in[7];
    const float* g_w1   = (const float*)d_in[8];
    const float* g_b1   = (const float*)d_in[9];
    const float* g_w2   = (const float*)d_in[10];
    const float* g_b2   = (const float*)d_in[11];
    const float* w_w    = (const float*)d_in[12];
    const float* w_b    = (const float*)d_in[13];
    const float* ldcy   = (const float*)d_in[14];
    const float* mix_re = (const float*)d_in[15];
    const float* mix_im = (const float*)d_in[16];
    const float* aw     = (const float*)d_in[17];
    const float* ag     = (const float*)d_in[18];

    float *ph, *pg, *pgmid, *pw1T, *pw2T, *pfc1T;
    cudaGetSymbolAddress((void**)&ph,    d_h);
    cudaGetSymbolAddress((void**)&pg,    d_g);
    cudaGetSymbolAddress((void**)&pgmid, d_gmid);
    cudaGetSymbolAddress((void**)&pw1T,  d_w1T);
    cudaGetSymbolAddress((void**)&pw2T,  d_w2T);
    cudaGetSymbolAddress((void**)&pfc1T, d_fc1T);

    fc0_kernel<<<dim3(128, 16), 128>>>(x_in, grid, fc0_w, fc0_b);
    zero_tail_kernel<<<1024, 256>>>();
    prep_weights_kernel<<<288, 256>>>(g_w1, g_w2, fc1_w);

    for (int i = 0; i < 4; i++) {
        conv1x1_kernel<64, 128, 1><<<dim3(130, 16), 256>>>(
            ph, pw1T + i * 8192, g_b1 + i * 128, pgmid, nullptr);
        if (i == 0) {
            init_ftab_kernel<<<(KPAD * 128 + 255) / 256, 256>>>();
            init_itab_kernel<<<(128 * XS + 255) / 256, 256>>>();
        }
        conv1x1_kernel<128, 64, 2><<<dim3(65, 16), 256>>>(
            pgmid, pw2T + i * 8192, g_b2 + i * 64, pg, ag);
        fdft_kernel<<<dim3(16, 18), 256>>>();
        reduce_kernel<<<1024, 256>>>();
        coefw_kernel<<<16, 256>>>(w_w, aw, i);
        modemix_kernel<<<dim3(16, 8), 512>>>(mix_re, mix_im, ldcy, w_b, aw, i);
        idft_kernel<<<dim3(65, 16), 256>>>((i < 3) ? 1 : 0);
    }

    conv1x1_kernel<64, 128, 1><<<dim3(128, 16), 256>>>(
        ph, pfc1T, fc1_b, pgmid, nullptr);
    fc2_kernel<<<dim3(128, 16), 128>>>(fc2_w, fc2_b, (float*)d_out);
}

// round 9
// speedup vs baseline: 1.8846x; 1.0252x over previous
#include <cuda_runtime.h>
#include <math.h>
#include <stdint.h>

#define XP    16386
#define XS    16640          // row stride (65*256)
#define NXV   16384
#define KPAD  16416          // forward-DFT K extent (18*912)
#define NB    16

// ------------------- static device buffers -------------------
__device__ float d_h   [(size_t)NB * 64 * XS];
__device__ float d_g   [(size_t)NB * 64 * XS];
__device__ float d_gmid[(size_t)NB * 128 * XS];
__device__ float d_ftab[(size_t)KPAD * 128];      // [x][2m]=cos, [2m+1]=-sin
__device__ float d_itab[(size_t)128 * XS];        // [2m][x]=cos, [2m+1][x]=sin
__device__ float d_part[(size_t)18 * 2048 * 128];
__device__ float d_fw  [2048 * 128];
__device__ float d_outm[1024 * 128];
__device__ float d_coefW[64 * 64];                // aw * W for current block
__device__ float d_w1T [4 * 64 * 128];
__device__ float d_w2T [4 * 128 * 64];
__device__ float d_fc1T[64 * 128];

// ------------------- f32x2 packed helpers -------------------
__device__ __forceinline__ uint64_t pack2(float lo, float hi) {
    uint64_t r;
    asm("mov.b64 %0, {%1, %2};" : "=l"(r) : "f"(lo), "f"(hi));
    return r;
}
__device__ __forceinline__ void unpack2(uint64_t v, float& lo, float& hi) {
    asm("mov.b64 {%0, %1}, %2;" : "=f"(lo), "=f"(hi) : "l"(v));
}
#define FMA2(d, a, b) \
    asm("fma.rn.f32x2 %0, %1, %2, %0;" : "+l"(d) : "l"(a), "l"(b))

__device__ __forceinline__ uint32_t s2u(const void* p) {
    return (uint32_t)__cvta_generic_to_shared(p);
}
__device__ __forceinline__ void cp16(uint32_t s, const float* g) {
    asm volatile("cp.async.cg.shared.global [%0], [%1], 16;"
                 :: "r"(s), "l"(__cvta_generic_to_global(g)));
}
#define CP_COMMIT asm volatile("cp.async.commit_group;")
#define CP_WAIT(n) asm volatile("cp.async.wait_group %0;" :: "n"(n))

__device__ __forceinline__ float softplus_(float x) {
    return (x > 20.f) ? x : log1pf(expf(x));
}
__device__ __forceinline__ float gelu_(float v) {
    return 0.5f * v * (1.0f + erff(v * 0.70710678118654752f));
}

// ------------------- mega setup kernel -------------------
// blocks [0,1024)      : fc0         (256 x-positions per block)
// blocks [1024,2048)   : zero h tail
// blocks [2048,2336)   : weight transposes
// blocks [2336,10544)  : ftab init
// blocks [10544,18864) : itab init
__global__ void __launch_bounds__(256) setup_kernel(
    const float* __restrict__ xin, const float* __restrict__ gin,
    const float* __restrict__ fc0_w, const float* __restrict__ fc0_b,
    const float* __restrict__ g_w1, const float* __restrict__ g_w2,
    const float* __restrict__ fc1_w)
{
    const int blk = blockIdx.x;
    const int tid = threadIdx.x;
    if (blk < 1024) {                             // ---- fc0 ----
        __shared__ float sw[64 * 32];
        __shared__ float sb[64];
        for (int l = tid; l < 64 * 31; l += 256) {
            int wo = l / 31, c = l - wo * 31;
            sw[wo * 32 + c] = fc0_w[l];
        }
        if (tid < 64) sb[tid] = fc0_b[tid];
        __syncthreads();
        int b = blk >> 6;
        int x = ((blk & 63) << 8) + tid;
        float rin[31];
        const float* xi = xin + ((size_t)b * NXV + x) * 30;
#pragma unroll
        for (int c = 0; c < 30; c++) rin[c] = __ldg(&xi[c]);
        rin[30] = __ldg(&gin[(size_t)b * NXV + x]);
        for (int wo = 0; wo < 64; wo++) {
            float acc = sb[wo];
#pragma unroll
            for (int c = 0; c < 31; c++) acc = fmaf(rin[c], sw[wo * 32 + c], acc);
            d_h[(size_t)(b * 64 + wo) * XS + x] = acc;
        }
    } else if (blk < 2048) {                      // ---- zero h tail ----
        int idx = (blk - 1024) * 256 + tid;       // 1024 rows x 256 cols
        int row = idx >> 8, col = NXV + (idx & 255);
        d_h[(size_t)row * XS + col] = 0.f;
    } else if (blk < 2336) {                      // ---- weight transposes ----
        int idx = (blk - 2048) * 256 + tid;
        if (idx < 32768) {
            int i = idx >> 13, r = idx & 8191, c = r >> 7, j = r & 127;
            d_w1T[idx] = g_w1[(i * 128 + j) * 64 + c];
        } else if (idx < 65536) {
            int t = idx - 32768;
            int i = t >> 13, r = t & 8191, j = r >> 6, o = r & 63;
            d_w2T[t] = g_w2[(i * 64 + o) * 128 + j];
        } else if (idx < 73728) {
            int t = idx - 65536;
            int c = t >> 7, j = t & 127;
            d_fc1T[t] = fc1_w[j * 64 + c];
        }
    } else if (blk < 10544) {                     // ---- ftab ----
        int idx = (blk - 2336) * 256 + tid;
        int x = idx >> 7, t = idx & 127, m = t >> 1;
        float v = 0.f;
        if (x < XP) {
            int u = (x * m) % XP;
            float s, c;
            sincospif(2.0f * (float)u / (float)XP, &s, &c);
            v = (t & 1) ? -s : c;
        }
        d_ftab[idx] = v;
    } else {                                      // ---- itab ----
        int idx = (blk - 10544) * 256 + tid;
        int t = idx / XS, x = idx - t * XS, m = t >> 1;
        float v = 0.f;
        if (x < XP) {
            int u = (x * m) % XP;
            float s, c;
            sincospif(2.0f * (float)u / (float)XP, &s, &c);
            v = (t & 1) ? s : c;
        }
        d_itab[idx] = v;
    }
}

__global__ void coefw_kernel(const float* __restrict__ w_w,
                             const float* __restrict__ alpha_w, int blk) {
    int i = blockIdx.x * 256 + threadIdx.x;      // 4096
    d_coefW[i] = softplus_(__ldg(alpha_w)) * __ldg(&w_w[blk * 4096 + i]);
}

// ------------------- 1x1 conv (cp.async double-buffered, f32x2) -------------------
// ACT: 0=none, 1=gelu, 2=scale by softplus(*alpha)
template<int CIN, int COUT, int ACT>
__global__ void __launch_bounds__(256, 2) conv1x1_kernel(
    const float* __restrict__ in,
    const float* __restrict__ wT,
    const float* __restrict__ bias,
    float* __restrict__ out,
    const float* __restrict__ alpha)
{
    constexpr int BP  = (COUT >= 128) ? 128 : 256;
    constexpr int TPp = BP / 32;
    constexpr int TOc = COUT / 8;
    constexpr int OP  = TOc / 2;
    constexpr int NTt = CIN / 16;
    constexpr int SIC = (16 * BP / 4) / 256;
    constexpr int SWC = (16 * COUT / 4) / 256;
    __shared__ float si [2][16][BP];
    __shared__ float swt[2][16][COUT];
    const int b   = blockIdx.y;
    const int p0  = blockIdx.x * BP;
    const int tid = threadIdx.x;
    const int po  = (tid & 31) * TPp;
    const int oo  = (tid >> 5) * TOc;

    const float* inb = in + (size_t)b * CIN * XS + p0;

    uint64_t acc[TPp][OP];
#pragma unroll
    for (int p = 0; p < TPp; p++)
#pragma unroll
        for (int j = 0; j < OP; j++) acc[p][j] = 0ull;

    {
#pragma unroll
        for (int l = 0; l < SIC; l++) {
            int c = l * 256 + tid;
            int k = c / (BP / 4), q = (c % (BP / 4)) * 4;
            cp16(s2u(&si[0][k][q]), inb + k * XS + q);
        }
#pragma unroll
        for (int l = 0; l < SWC; l++) {
            int c = l * 256 + tid;
            int k = c / (COUT / 4), q = (c % (COUT / 4)) * 4;
            cp16(s2u(&swt[0][k][q]), wT + k * COUT + q);
        }
        CP_COMMIT;
    }
#pragma unroll
    for (int t = 0; t < NTt; t++) {
        const int buf = t & 1;
        if (t + 1 < NTt) {
            const int c0 = (t + 1) * 16;
#pragma unroll
            for (int l = 0; l < SIC; l++) {
                int c = l * 256 + tid;
                int k = c / (BP / 4), q = (c % (BP / 4)) * 4;
                cp16(s2u(&si[buf ^ 1][k][q]), inb + (c0 + k) * XS + q);
            }
#pragma unroll
            for (int l = 0; l < SWC; l++) {
                int c = l * 256 + tid;
                int k = c / (COUT / 4), q = (c % (COUT / 4)) * 4;
                cp16(s2u(&swt[buf ^ 1][k][q]), wT + (c0 + k) * COUT + q);
            }
            CP_COMMIT;
            CP_WAIT(1);
        } else {
            CP_WAIT(0);
        }
        __syncthreads();
#pragma unroll
        for (int k = 0; k < 16; k++) {
            uint64_t pa[TPp];
#pragma unroll
            for (int u = 0; u < TPp / 4; u++) {
                float4 av = *(const float4*)&si[buf][k][po + 4 * u];
                pa[4*u+0] = pack2(av.x, av.x);
                pa[4*u+1] = pack2(av.y, av.y);
                pa[4*u+2] = pack2(av.z, av.z);
                pa[4*u+3] = pack2(av.w, av.w);
            }
#pragma unroll
            for (int j = 0; j < OP; j++) {
                uint64_t wv = *(const uint64_t*)&swt[buf][k][oo + 2 * j];
#pragma unroll
                for (int p = 0; p < TPp; p++) FMA2(acc[p][j], wv, pa[p]);
            }
        }
        __syncthreads();
    }

    float scv = 1.f;
    if (ACT == 2) scv = softplus_(__ldg(alpha));
#pragma unroll
    for (int j = 0; j < OP; j++) {
        int o0 = oo + 2 * j;
        float b0 = __ldg(&bias[o0]);
        float b1 = __ldg(&bias[o0 + 1]);
        float vlo[TPp], vhi[TPp];
#pragma unroll
        for (int p = 0; p < TPp; p++) {
            unpack2(acc[p][j], vlo[p], vhi[p]);
            vlo[p] += b0; vhi[p] += b1;
            if (ACT == 1) { vlo[p] = gelu_(vlo[p]); vhi[p] = gelu_(vhi[p]); }
            if (ACT == 2) { vlo[p] *= scv; vhi[p] *= scv; }
        }
        float* r0 = out + ((size_t)b * COUT + o0) * XS + p0 + po;
        float* r1 = r0 + XS;
#pragma unroll
        for (int q = 0; q < TPp / 4; q++) {
            *(float4*)&r0[4*q] = make_float4(vlo[4*q], vlo[4*q+1], vlo[4*q+2], vlo[4*q+3]);
            *(float4*)&r1[4*q] = make_float4(vhi[4*q], vhi[4*q+1], vhi[4*q+2], vhi[4*q+3]);
        }
    }
}

// -------- forward DFT: dup-broadcast rows (LDG prefetch), ftab via cp.async --------
__global__ void __launch_bounds__(256, 2) fdft_kernel() {
    const int rt = blockIdx.x;     // 0..15 : 128-row tiles (8 h, 8 g)
    const int ks = blockIdx.y;     // 0..17 : K splits of 912 (57 tiles)
    const float* src = (rt < 8) ? d_h + (size_t)rt * 128 * XS
                                : d_g + (size_t)(rt - 8) * 128 * XS;
    const int kbase = ks * 912;

    __shared__ float sa[2][16][260];   // rows DUPLICATED: [k][2*row]
    __shared__ float sf[2][16][128];   // ftab straight [k][comp] (cp.async)
    const int tid = threadIdx.x;
    const int cg = tid & 15;
    const int rg = tid >> 4;

    uint64_t acc[8][4];
#pragma unroll
    for (int r = 0; r < 8; r++)
#pragma unroll
        for (int j = 0; j < 4; j++) acc[r][j] = 0ull;

    float ra[8];
    // prefetch tile 0
#pragma unroll
    for (int l = 0; l < 2; l++) {
        int c = l * 256 + tid;
        cp16(s2u(&sf[0][c >> 5][(c & 31) * 4]),
             &d_ftab[(size_t)(kbase + (c >> 5)) * 128 + (c & 31) * 4]);
    }
    CP_COMMIT;
#pragma unroll
    for (int l = 0; l < 8; l++) {
        int c = l * 256 + tid;
        ra[l] = src[(size_t)(c >> 4) * XS + kbase + (c & 15)];
    }
#pragma unroll
    for (int l = 0; l < 8; l++) {
        int c = l * 256 + tid;
        *(uint64_t*)&sa[0][c & 15][2 * (c >> 4)] = pack2(ra[l], ra[l]);
    }
    CP_WAIT(0);
    __syncthreads();

    for (int t = 0; t < 57; t++) {
        const int buf = t & 1;
        if (t < 56) {
            const int kb = kbase + (t + 1) * 16;
#pragma unroll
            for (int l = 0; l < 2; l++) {
                int c = l * 256 + tid;
                cp16(s2u(&sf[buf ^ 1][c >> 5][(c & 31) * 4]),
                     &d_ftab[(size_t)(kb + (c >> 5)) * 128 + (c & 31) * 4]);
            }
            CP_COMMIT;
#pragma unroll
            for (int l = 0; l < 8; l++) {
                int c = l * 256 + tid;
                ra[l] = src[(size_t)(c >> 4) * XS + kb + (c & 15)];
            }
        }
#pragma unroll
        for (int k = 0; k < 16; k++) {
            ulonglong2 c0 = *(const ulonglong2*)&sf[buf][k][cg * 4];
            ulonglong2 c1 = *(const ulonglong2*)&sf[buf][k][64 + cg * 4];
            ulonglong2 r01 = *(const ulonglong2*)&sa[buf][k][rg * 16];
            ulonglong2 r23 = *(const ulonglong2*)&sa[buf][k][rg * 16 + 4];
            ulonglong2 r45 = *(const ulonglong2*)&sa[buf][k][rg * 16 + 8];
            ulonglong2 r67 = *(const ulonglong2*)&sa[buf][k][rg * 16 + 12];
            uint64_t rd[8] = {r01.x, r01.y, r23.x, r23.y, r45.x, r45.y, r67.x, r67.y};
#pragma unroll
            for (int r = 0; r < 8; r++) {
                FMA2(acc[r][0], rd[r], c0.x);
                FMA2(acc[r][1], rd[r], c0.y);
                FMA2(acc[r][2], rd[r], c1.x);
                FMA2(acc[r][3], rd[r], c1.y);
            }
        }
        if (t < 56) {
#pragma unroll
            for (int l = 0; l < 8; l++) {
                int c = l * 256 + tid;
                *(uint64_t*)&sa[buf ^ 1][c & 15][2 * (c >> 4)] = pack2(ra[l], ra[l]);
            }
            CP_WAIT(0);
        }
        __syncthreads();
    }
#pragma unroll
    for (int r = 0; r < 8; r++) {
        int row = rt * 128 + rg * 8 + r;
        float4 v0, v1;
        unpack2(acc[r][0], v0.x, v0.y);
        unpack2(acc[r][1], v0.z, v0.w);
        unpack2(acc[r][2], v1.x, v1.y);
        unpack2(acc[r][3], v1.z, v1.w);
        float* pp = &d_part[((size_t)ks * 2048 + row) * 128];
        *(float4*)&pp[cg * 4]      = v0;
        *(float4*)&pp[64 + cg * 4] = v1;
    }
}

__global__ void reduce_kernel() {
    int idx = blockIdx.x * 256 + threadIdx.x;   // 262144
    float s = 0.f;
#pragma unroll
    for (int k = 0; k < 18; k++) s += d_part[(size_t)k * 262144 + idx];
    d_fw[idx] = s;
}

// ------------------- mode mix + ETD coefficients (bias folded at m=0) -------------------
__global__ void __launch_bounds__(512) modemix_kernel(const float* __restrict__ mix_re,
                                                      const float* __restrict__ mix_im,
                                                      const float* __restrict__ log_decay,
                                                      const float* __restrict__ w_b,
                                                      const float* __restrict__ alpha_w,
                                                      int blk) {
    __shared__ float sg[64 * 128];
    const int b  = blockIdx.x;
    const int og = blockIdx.y;
    const int tid = threadIdx.x;
#pragma unroll
    for (int l = 0; l < 16; l++) {
        int idx = l * 512 + tid;
        sg[idx] = d_fw[(size_t)(1024 + b * 64) * 128 + idx];
    }
    __syncthreads();
    const int m = tid & 63, ol = tid >> 6;
    const int o = og * 8 + ol;
    const float* mr = mix_re + (size_t)blk * 262144 + o * 64 + m;
    const float* mi = mix_im + (size_t)blk * 262144 + o * 64 + m;
    float ar = 0.f, ai = 0.f;
#pragma unroll 4
    for (int i = 0; i < 64; i++) {
        float2 gh = *(const float2*)&sg[i * 128 + 2 * m];
        float r_ = __ldg(&mr[(size_t)i * 4096]);
        float i_ = __ldg(&mi[(size_t)i * 4096]);
        ar = fmaf(gh.x, r_, ar); ar = fmaf(-gh.y, i_, ar);
        ai = fmaf(gh.x, i_, ai); ai = fmaf( gh.y, r_, ai);
    }
    float ld = __ldg(&log_decay[((size_t)blk * 64 + o) * 64 + m]);
    float z  = -softplus_(ld);
    float ez = expf(z);
    float phi = (fabsf(z) < 1e-6f) ? (1.f + 0.5f * z + z * z * (1.f / 6.f))
                                   : (expm1f(z) / z);
    float gq = (float)m * (1.f / 63.f);
    float r2 = gq * gq + 1e-12f;
    float r8 = r2 * r2; r8 = r8 * r8;
    float pf = phi * expf(-2.f * r8);

    size_t vrow = ((size_t)b * 64 + o) * 128;
    float vr = d_fw[vrow + 2 * m], vi = d_fw[vrow + 2 * m + 1];
    float outr = fmaf(ez, vr, pf * ar);
    float outi = fmaf(ez, vi, pf * ai);
    const float inv = 1.0f / 16386.0f;
    float resr = (m == 0) ? outr * inv : 2.f * outr * inv;
    if (m == 0) resr += softplus_(__ldg(alpha_w)) * __ldg(&w_b[blk * 64 + o]);
    d_outm[vrow + 2 * m]     = resr;
    d_outm[vrow + 2 * m + 1] = (m == 0) ? 0.f : -2.f * outi * inv;
}

// ---- inverse DFT + fused w-skip + act (coef dup via LDG, x-strips via cp.async) ----
__global__ void __launch_bounds__(256, 2) idft_kernel(int act) {
    const int x0 = blockIdx.x * 256;
    const int b  = blockIdx.y;
    __shared__ float st[2][16][256];   // [k][x] straight (cp.async)
    __shared__ float sc[2][16][136];   // coef DUP [k][2*row]
    const int tid = threadIdx.x;
    const int xg = tid & 15;
    const int rg = tid >> 4;
    float* hb = d_h + (size_t)b * 64 * XS;

    uint64_t acc[4][8];
#pragma unroll
    for (int r = 0; r < 4; r++)
#pragma unroll
        for (int j = 0; j < 8; j++) acc[r][j] = 0ull;

    float rc[4];
    // prefetch tile 0
#pragma unroll
    for (int l = 0; l < 4; l++) {
        int c = l * 256 + tid;
        cp16(s2u(&st[0][c >> 6][(c & 63) * 4]),
             &d_itab[(size_t)(c >> 6) * XS + x0 + (c & 63) * 4]);
    }
    CP_COMMIT;
#pragma unroll
    for (int l = 0; l < 4; l++) {
        int c = l * 256 + tid;
        rc[l] = d_outm[(size_t)(b * 64 + (c >> 4)) * 128 + (c & 15)];
    }
#pragma unroll
    for (int l = 0; l < 4; l++) {
        int c = l * 256 + tid;
        *(uint64_t*)&sc[0][c & 15][2 * (c >> 4)] = pack2(rc[l], rc[l]);
    }
    CP_WAIT(0);
    __syncthreads();

#pragma unroll
    for (int t = 0; t < 12; t++) {
        const int buf = t & 1;
        if (t < 11) {
            const int kb = (t + 1) * 16;
#pragma unroll
            for (int l = 0; l < 4; l++) {
                int c = l * 256 + tid;
                int k = c >> 6, q = (c & 63) * 4;
                const float* gsrc = (kb < 128)
                    ? &d_itab[(size_t)(kb + k) * XS + x0 + q]
                    : &hb[(size_t)(kb - 128 + k) * XS + x0 + q];
                cp16(s2u(&st[buf ^ 1][k][q]), gsrc);
            }
            CP_COMMIT;
#pragma unroll
            for (int l = 0; l < 4; l++) {
                int c = l * 256 + tid;
                int k = c & 15, row = c >> 4;
                rc[l] = (kb < 128)
                    ? d_outm[(size_t)(b * 64 + row) * 128 + kb + k]
                    : d_coefW[row * 64 + (kb - 128) + k];
            }
        }
#pragma unroll
        for (int k = 0; k < 16; k++) {
            ulonglong2 w01 = *(const ulonglong2*)&sc[buf][k][rg * 8];
            ulonglong2 w23 = *(const ulonglong2*)&sc[buf][k][rg * 8 + 4];
            uint64_t wd[4] = {w01.x, w01.y, w23.x, w23.y};
#pragma unroll
            for (int c = 0; c < 4; c++) {
                ulonglong2 xv = *(const ulonglong2*)&st[buf][k][c * 64 + xg * 4];
#pragma unroll
                for (int r = 0; r < 4; r++) {
                    FMA2(acc[r][2 * c],     wd[r], xv.x);
                    FMA2(acc[r][2 * c + 1], wd[r], xv.y);
                }
            }
        }
        if (t < 11) {
#pragma unroll
            for (int l = 0; l < 4; l++) {
                int c = l * 256 + tid;
                *(uint64_t*)&sc[buf ^ 1][c & 15][2 * (c >> 4)] = pack2(rc[l], rc[l]);
            }
            CP_WAIT(0);
        }
        __syncthreads();
    }
#pragma unroll
    for (int r = 0; r < 4; r++) {
        int row = rg * 4 + r;
#pragma unroll
        for (int c = 0; c < 4; c++) {
            float4 v;
            unpack2(acc[r][2 * c],     v.x, v.y);
            unpack2(acc[r][2 * c + 1], v.z, v.w);
            if (act) { v.x = gelu_(v.x); v.y = gelu_(v.y); v.z = gelu_(v.z); v.w = gelu_(v.w); }
            *(float4*)&hb[(size_t)row * XS + x0 + c * 64 + xg * 4] = v;
        }
    }
}

// ------------------- fc2 -------------------
__global__ void __launch_bounds__(128) fc2_kernel(const float* __restrict__ w,
                                                  const float* __restrict__ bias,
                                                  float* __restrict__ out) {
    __shared__ float sw[3][128];
    int tid = threadIdx.x;
    for (int l = tid; l < 384; l += 128) sw[l >> 7][l & 127] = w[l];
    __syncthreads();
    int b = blockIdx.y;
    int x = blockIdx.x * 128 + tid;
    float a0 = __ldg(&bias[0]), a1 = __ldg(&bias[1]), a2 = __ldg(&bias[2]);
#pragma unroll 4
    for (int j = 0; j < 128; j++) {
        float v = d_gmid[((size_t)b * 128 + j) * XS + x];
        a0 = fmaf(v, sw[0][j], a0);
        a1 = fmaf(v, sw[1][j], a1);
        a2 = fmaf(v, sw[2][j], a2);
    }
    size_t o = ((size_t)b * NXV + x) * 3;
    out[o] = a0; out[o + 1] = a1; out[o + 2] = a2;
}

// ------------------- launch -------------------
extern "C" void kernel_launch(void* const* d_in, const int* in_sizes, int n_in,
                              void* d_out, int out_size) {
    const float* x_in   = (const float*)d_in[0];
    const float* grid   = (const float*)d_in[1];
    const float* fc0_w  = (const float*)d_in[2];
    const float* fc0_b  = (const float*)d_in[3];
    const float* fc1_w  = (const float*)d_in[4];
    const float* fc1_b  = (const float*)d_in[5];
    const float* fc2_w  = (const float*)d_in[6];
    const float* fc2_b  = (const float*)d_in[7];
    const float* g_w1   = (const float*)d_in[8];
    const float* g_b1   = (const float*)d_in[9];
    const float* g_w2   = (const float*)d_in[10];
    const float* g_b2   = (const float*)d_in[11];
    const float* w_w    = (const float*)d_in[12];
    const float* w_b    = (const float*)d_in[13];
    const float* ldcy   = (const float*)d_in[14];
    const float* mix_re = (const float*)d_in[15];
    const float* mix_im = (const float*)d_in[16];
    const float* aw     = (const float*)d_in[17];
    const float* ag     = (const float*)d_in[18];

    float *ph, *pg, *pgmid, *pw1T, *pw2T, *pfc1T;
    cudaGetSymbolAddress((void**)&ph,    d_h);
    cudaGetSymbolAddress((void**)&pg,    d_g);
    cudaGetSymbolAddress((void**)&pgmid, d_gmid);
    cudaGetSymbolAddress((void**)&pw1T,  d_w1T);
    cudaGetSymbolAddress((void**)&pw2T,  d_w2T);
    cudaGetSymbolAddress((void**)&pfc1T, d_fc1T);

    // launch 1: everything fdft needs except the two convs
    setup_kernel<<<18864, 256>>>(x_in, grid, fc0_w, fc0_b, g_w1, g_w2, fc1_w);

    for (int i = 0; i < 4; i++) {
        conv1x1_kernel<64, 128, 1><<<dim3(130, 16), 256>>>(
            ph, pw1T + i * 8192, g_b1 + i * 128, pgmid, nullptr);
        conv1x1_kernel<128, 64, 2><<<dim3(65, 16), 256>>>(
            pgmid, pw2T + i * 8192, g_b2 + i * 64, pg, ag);
        fdft_kernel<<<dim3(16, 18), 256>>>();       // launch #4 on i==0 -> ncu capture
        reduce_kernel<<<1024, 256>>>();
        coefw_kernel<<<16, 256>>>(w_w, aw, i);
        modemix_kernel<<<dim3(16, 8), 512>>>(mix_re, mix_im, ldcy, w_b, aw, i);
        idft_kernel<<<dim3(65, 16), 256>>>((i < 3) ? 1 : 0);
    }

    conv1x1_kernel<64, 128, 1><<<dim3(128, 16), 256>>>(
        ph, pfc1T, fc1_b, pgmid, nullptr);
    fc2_kernel<<<dim3(128, 16), 128>>>(fc2_w, fc2_b, (float*)d_out);
}